// round 12
// baseline (speedup 1.0000x reference)
#include <cuda_runtime.h>
#include <cuda_bf16.h>
#include <math.h>
#include <cstdint>

#define BB 16
#define NT 16

// ---------------- persistent scratch (device globals; no allocation) -------
__device__ float g_h [16*64*1024];     // attended h (recurrent carry)
__device__ float g_hg[16*64*1024];     // pre-attention h (gate output)
__device__ float g_c [16*64*1024];     // cell state
__device__ float g_q [16*16*1024];
__device__ float g_conv[16*256*1024];  // conv output (B,256,32,32), pre-bias
// packed bf16x2 hi/lo k and v (written by k_qkv, read by k_flash)
__device__ uint32_t g_k2h[16*1024*8];  // [b][m][c2]
__device__ uint32_t g_k2l[16*1024*8];
__device__ uint32_t g_v2h[16*64*512];  // [b][c][mp]
__device__ uint32_t g_v2l[16*64*512];
// bf16 hi/lo split conv weights in mma-fragment-linear order
__device__ uint32_t g_Wfrag[294912];

// ---------------- init: zero h and c ---------------------------------------
__global__ void k_init()
{
    int i = blockIdx.x * 256 + threadIdx.x;
    g_h[i] = 0.f;
    g_c[i] = 0.f;
}

__device__ __forceinline__ float sigf(float x) { return 1.f / (1.f + __expf(-x)); }
__device__ __forceinline__ float tanh_fast(float x)
{
    return __fdividef(2.f, 1.f + __expf(-2.f * x)) - 1.f;
}
__device__ __forceinline__ uint32_t pack_bf16(float a, float b)
{
    __nv_bfloat162 h2 = __floats2bfloat162_rn(a, b);
    return *reinterpret_cast<uint32_t*>(&h2);
}
__device__ __forceinline__ float bf16_lo(float a)
{
    return a - __bfloat162float(__float2bfloat16(a));
}
__device__ __forceinline__ void mma_bf16(float* c, uint4 a, uint2 b)
{
    asm volatile(
        "mma.sync.aligned.m16n8k16.row.col.f32.bf16.bf16.f32 "
        "{%0,%1,%2,%3}, {%4,%5,%6,%7}, {%8,%9}, {%0,%1,%2,%3};"
        : "+f"(c[0]), "+f"(c[1]), "+f"(c[2]), "+f"(c[3])
        : "r"(a.x), "r"(a.y), "r"(a.z), "r"(a.w), "r"(b.x), "r"(b.y));
}

// ---------------- weight prep: split + fragment-linear layout --------------
__global__ void k_prepw(const float* __restrict__ Wc)
{
    int idx   = blockIdx.x * 256 + threadIdx.x;   // 294912
    int inner = idx & 4095;
    int outer = idx >> 12;
    int c0    = outer % 18;
    int gate  = outer / 18;
    int s     = inner & 1;
    int lane  = (inner >> 1) & 31;
    int ki    = (inner >> 6) & 3;
    int ni    = (inner >> 8) & 7;
    int sp    = (inner >> 11) & 1;

    int g = lane >> 2, tt = lane & 3;
    int n_global = gate * 64 + ni * 8 + g;
    int k0 = c0 * 64 + ki * 16 + 2 * tt + 8 * s;

    float w0, w1;
    {
        int ci = k0 / 9, r = k0 - ci * 9;
        w0 = Wc[(n_global * 128 + ci) * 9 + r];
        int k1 = k0 + 1;
        ci = k1 / 9; r = k1 - ci * 9;
        w1 = Wc[(n_global * 128 + ci) * 9 + r];
    }
    if (sp == 1) { w0 = bf16_lo(w0); w1 = bf16_lo(w1); }
    g_Wfrag[idx] = pack_bf16(w0, w1);
}

// ---------------- conv via mma.sync bf16 (R10 winner, unchanged) -----------
__global__ void __launch_bounds__(256, 2) k_conv_mma(
    const float* __restrict__ X, int t)
{
    __shared__ uint32_t sm_u[12288];       // 48 KB: Ah|Al|Bh|Bl
    uint32_t* Ah_s = sm_u;
    uint32_t* Al_s = sm_u + 4096;
    uint32_t* Bh_s = sm_u + 8192;
    uint32_t* Bl_s = sm_u + 10240;

    const int tid  = threadIdx.x;
    const int wid  = tid >> 5;
    const int lane = tid & 31;
    const int mt   = blockIdx.x;
    const int b    = blockIdx.y;
    const int gate = blockIdx.z;
    const int n0   = gate * 64;
    const int wm   = wid >> 1;
    const int wn   = wid & 1;
    const int g    = lane >> 2, tt = lane & 3;

    const float* Xb = X + (b * 64 * 16 + t) * 1024;
    const float* Hb = g_h + b * 64 * 1024;

    float acc[2][4][4];
    #pragma unroll
    for (int im = 0; im < 2; ++im)
        #pragma unroll
        for (int in = 0; in < 4; ++in)
            #pragma unroll
            for (int q = 0; q < 4; ++q) acc[im][in][q] = 0.f;

    const uint4* Ah4 = reinterpret_cast<const uint4*>(Ah_s);
    const uint4* Al4 = reinterpret_cast<const uint4*>(Al_s);
    const uint2* Bh2 = reinterpret_cast<const uint2*>(Bh_s);
    const uint2* Bl2 = reinterpret_cast<const uint2*>(Bl_s);

    for (int c0 = 0; c0 < 18; ++c0) {
        #pragma unroll
        for (int j = 0; j < 16; ++j) {
            int slot = j * 256 + tid;
            int s  = slot & 3;
            int ln = (slot >> 2) & 31;
            int ki = (slot >> 7) & 3;
            int mi = slot >> 9;
            int gg = ln >> 2, t4 = ln & 3;
            int m  = mi * 16 + gg + 8 * (s & 1);
            int kb = c0 * 64 + ki * 16 + 2 * t4 + 8 * (s >> 1);
            int pix = mt * 128 + m;
            int py = pix >> 5, px = pix & 31;
            float a0 = 0.f, a1 = 0.f;
            #pragma unroll
            for (int h = 0; h < 2; ++h) {
                int kg = kb + h;
                int ci = kg / 9, r = kg - ci * 9;
                int dy = r / 3 - 1, dx = r - (r / 3) * 3 - 1;
                int ys = py + dy, xs = px + dx;
                float a = 0.f;
                if ((unsigned)ys < 32u && (unsigned)xs < 32u) {
                    int sp2 = ys * 32 + xs;
                    a = (ci < 64) ? Xb[ci * 16384 + sp2]
                                  : Hb[(ci - 64) * 1024 + sp2];
                }
                if (h == 0) a0 = a; else a1 = a;
            }
            Ah_s[slot] = pack_bf16(a0, a1);
            Al_s[slot] = pack_bf16(bf16_lo(a0), bf16_lo(a1));
        }
        {
            const uint4* src = reinterpret_cast<const uint4*>(
                g_Wfrag + (gate * 18 + c0) * 4096);
            uint4* dh = reinterpret_cast<uint4*>(Bh_s);
            uint4* dl = reinterpret_cast<uint4*>(Bl_s);
            dh[tid]       = src[tid];
            dh[tid + 256] = src[tid + 256];
            dl[tid]       = src[tid + 512];
            dl[tid + 256] = src[tid + 768];
        }
        __syncthreads();

        #pragma unroll
        for (int ki = 0; ki < 4; ++ki) {
            uint4 a0h = Ah4[((wm * 2    ) * 4 + ki) * 32 + lane];
            uint4 a1h = Ah4[((wm * 2 + 1) * 4 + ki) * 32 + lane];
            uint4 a0l = Al4[((wm * 2    ) * 4 + ki) * 32 + lane];
            uint4 a1l = Al4[((wm * 2 + 1) * 4 + ki) * 32 + lane];
            #pragma unroll
            for (int in = 0; in < 4; ++in) {
                int ni = wn * 4 + in;
                uint2 bh = Bh2[(ni * 4 + ki) * 32 + lane];
                uint2 bl = Bl2[(ni * 4 + ki) * 32 + lane];
                mma_bf16(acc[0][in], a0h, bh);
                mma_bf16(acc[1][in], a1h, bh);
                mma_bf16(acc[0][in], a0h, bl);
                mma_bf16(acc[1][in], a1h, bl);
                mma_bf16(acc[0][in], a0l, bh);
                mma_bf16(acc[1][in], a1l, bh);
            }
        }
        __syncthreads();
    }

    float* out_s = reinterpret_cast<float*>(sm_u);
    #pragma unroll
    for (int im = 0; im < 2; ++im) {
        int mi = wm * 2 + im;
        int m  = mi * 16 + g;
        #pragma unroll
        for (int in = 0; in < 4; ++in) {
            int ni = wn * 4 + in;
            int n  = ni * 8 + 2 * tt;
            out_s[ n      * 132 + m    ] = acc[im][in][0];
            out_s[(n + 1) * 132 + m    ] = acc[im][in][1];
            out_s[ n      * 132 + m + 8] = acc[im][in][2];
            out_s[(n + 1) * 132 + m + 8] = acc[im][in][3];
        }
    }
    __syncthreads();
    #pragma unroll
    for (int j = 0; j < 32; ++j) {
        int idx = j * 256 + tid;
        int n = idx >> 7, m = idx & 127;
        g_conv[(b * 256 + n0 + n) * 1024 + mt * 128 + m] = out_s[n * 132 + m];
    }
}

// ---------------- ConvLSTM gating (elementwise) ----------------------------
__global__ void k_gate(const float* __restrict__ bc,
                       const float* __restrict__ Wci,
                       const float* __restrict__ Wcf,
                       const float* __restrict__ Wco)
{
    int idx = blockIdx.x * 256 + threadIdx.x;
    int b   = idx >> 16;
    int c   = (idx >> 10) & 63;
    int pos = idx & 1023;
    int cb  = (b * 256 + c) * 1024 + pos;

    float ic = g_conv[cb]              + bc[c];
    float fc = g_conv[cb + 64 * 1024]  + bc[64 + c];
    float gc = g_conv[cb + 128 * 1024] + bc[128 + c];
    float oc = g_conv[cb + 192 * 1024] + bc[192 + c];
    float cp = g_c[idx];
    int   wp = c * 1024 + pos;

    float i  = sigf(ic + Wci[wp] * cp);
    float f  = sigf(fc + Wcf[wp] * cp);
    float nc = f * cp + i * tanh_fast(gc);
    float o  = sigf(oc + Wco[wp] * nc);
    g_c[idx]  = nc;
    g_hg[idx] = o * tanh_fast(nc);
}

// ---------------- q,k,v 1x1 convs; k/v packed to bf16 hi/lo ---------------
__global__ void k_qkv(const float* __restrict__ qw, const float* __restrict__ qb,
                      const float* __restrict__ kw, const float* __restrict__ kb,
                      const float* __restrict__ vw, const float* __restrict__ vb)
{
    __shared__ float h_s[32 * 256];
    __shared__ float w_s[8 * 64];

    const int p0  = blockIdx.x * 256;
    const int oc0 = blockIdx.y * 8;
    const int b   = blockIdx.z;
    const int tid = threadIdx.x;

    for (int i = tid; i < 512; i += 256) {
        int j = i >> 6; int c = i & 63; int oc = oc0 + j;
        w_s[i] = (oc < 16) ? qw[oc * 64 + c]
               : (oc < 32) ? kw[(oc - 16) * 64 + c]
                           : vw[(oc - 32) * 64 + c];
    }

    float acc[8];
    #pragma unroll
    for (int j = 0; j < 8; ++j) {
        int oc = oc0 + j;
        acc[j] = (oc < 16) ? qb[oc] : (oc < 32) ? kb[oc - 16] : vb[oc - 32];
    }

    for (int chh = 0; chh < 2; ++chh) {
        __syncthreads();
        for (int i = tid; i < 8192; i += 256) {
            int c = i >> 8; int j = i & 255;
            h_s[i] = g_hg[(b * 64 + chh * 32 + c) * 1024 + p0 + j];
        }
        __syncthreads();
        #pragma unroll 8
        for (int c = 0; c < 32; ++c) {
            float hv = h_s[c * 256 + tid];
            #pragma unroll
            for (int j = 0; j < 8; ++j)
                acc[j] += w_s[j * 64 + chh * 32 + c] * hv;
        }
    }

    int pos = p0 + tid;
    if (oc0 < 16) {
        #pragma unroll
        for (int j = 0; j < 8; ++j)
            g_q[(b * 16 + oc0 + j) * 1024 + pos] = acc[j];
    } else if (oc0 < 32) {
        #pragma unroll
        for (int jj = 0; jj < 4; ++jj) {
            float k0 = acc[2 * jj], k1 = acc[2 * jj + 1];
            int c2 = ((oc0 - 16) >> 1) + jj;
            int o  = (b * 1024 + pos) * 8 + c2;
            g_k2h[o] = pack_bf16(k0, k1);
            g_k2l[o] = pack_bf16(bf16_lo(k0), bf16_lo(k1));
        }
    } else {
        int vc0 = oc0 - 32;
        #pragma unroll
        for (int j = 0; j < 8; ++j) {
            float other = __shfl_xor_sync(0xffffffffu, acc[j], 1);
            if ((tid & 1) == 0) {
                int o = (b * 64 + vc0 + j) * 512 + (pos >> 1);
                g_v2h[o] = pack_bf16(acc[j], other);
                g_v2l[o] = pack_bf16(bf16_lo(acc[j]), bf16_lo(other));
            }
        }
    }
}

// ---------------- flash attention, in-block split-KV (512 threads) ---------
// grid (8 n-tiles of 128 rows, 16 batch), 512 threads = 16 warps.
// Warps 0-7 = half 0 (m-chunks 0-7), warps 8-15 = half 1 (chunks 8-15).
// Each half has its own 6144-u32 smem buffer + named barrier; online-softmax
// states merged exactly at the end (split-KV combine).
__global__ void __launch_bounds__(512) k_flash(
    const float* __restrict__ zw, const float* __restrict__ zb,
    float* __restrict__ out, int t)
{
    __shared__ uint32_t pool[12288];               // 48 KB: 2 x 6144 halves

    const int b    = blockIdx.y;
    const int n0   = blockIdx.x * 128;
    const int tid  = threadIdx.x;
    const int half = tid >> 8;                     // 0 or 1
    const int ht   = tid & 255;                    // half-local tid
    const int w8   = (tid >> 5) & 7;               // warp within half
    const int lane = tid & 31;
    const int g    = lane >> 2, tt = lane & 3;
    const int rA   = w8 * 16 + g;

    uint32_t* buf = pool + half * 6144;

    // ---- stage q tile (shared by both halves), build frags ----
    float* q_s = reinterpret_cast<float*>(pool);   // [128][17] = 2176
    for (int i = tid; i < 2048; i += 512) {
        int c = i >> 7, r = i & 127;
        q_s[r * 17 + c] = g_q[(b * 16 + c) * 1024 + n0 + r];
    }
    __syncthreads();
    uint4 qh, ql;
    {
        float x0 = q_s[rA * 17 + 2 * tt],           x1 = q_s[rA * 17 + 2 * tt + 1];
        float x2 = q_s[(rA + 8) * 17 + 2 * tt],     x3 = q_s[(rA + 8) * 17 + 2 * tt + 1];
        float x4 = q_s[rA * 17 + 8 + 2 * tt],       x5 = q_s[rA * 17 + 9 + 2 * tt];
        float x6 = q_s[(rA + 8) * 17 + 8 + 2 * tt], x7 = q_s[(rA + 8) * 17 + 9 + 2 * tt];
        qh = make_uint4(pack_bf16(x0, x1), pack_bf16(x2, x3),
                        pack_bf16(x4, x5), pack_bf16(x6, x7));
        ql = make_uint4(pack_bf16(bf16_lo(x0), bf16_lo(x1)),
                        pack_bf16(bf16_lo(x2), bf16_lo(x3)),
                        pack_bf16(bf16_lo(x4), bf16_lo(x5)),
                        pack_bf16(bf16_lo(x6), bf16_lo(x7)));
    }
    __syncthreads();

    float z[8][4];
    #pragma unroll
    for (int cj = 0; cj < 8; ++cj)
        #pragma unroll
        for (int q = 0; q < 4; ++q) z[cj][q] = 0.f;
    float Ma = -1e30f, Mb = -1e30f, la = 0.f, lb = 0.f;

    for (int cc = 0; cc < 8; ++cc) {
        const int mch = half * 8 + cc;
        // ---- stage this half's chunk (direct LDG -> STS) ----
        #pragma unroll
        for (int r = 0; r < 2; ++r) {
            int i = ht + r * 256;
            int m = i >> 3, c2 = i & 7;
            int src = (b * 1024 + mch * 64 + m) * 8 + c2;
            buf[m * 12 + c2]       = g_k2h[src];
            buf[768 + m * 12 + c2] = g_k2l[src];
        }
        #pragma unroll
        for (int r = 0; r < 8; ++r) {
            int i = ht + r * 256;
            int c = i >> 5, mp = i & 31;
            int src = (b * 64 + c) * 512 + mch * 32 + mp;
            buf[1536 + c * 36 + mp] = g_v2h[src];
            buf[3840 + c * 36 + mp] = g_v2l[src];
        }
        asm volatile("bar.sync %0, %1;" :: "r"(1 + half), "r"(256) : "memory");

        // ---- S = q . k^T (128 x 64), 3-pass hi/lo ----
        float S[8][4];
        #pragma unroll
        for (int j = 0; j < 8; ++j)
            #pragma unroll
            for (int q = 0; q < 4; ++q) S[j][q] = 0.f;
        #pragma unroll
        for (int j = 0; j < 8; ++j) {
            int m = j * 8 + g;
            uint2 bh = make_uint2(buf[m * 12 + tt],       buf[m * 12 + tt + 4]);
            uint2 bl = make_uint2(buf[768 + m * 12 + tt], buf[768 + m * 12 + tt + 4]);
            mma_bf16(S[j], qh, bh);
            mma_bf16(S[j], qh, bl);
            mma_bf16(S[j], ql, bh);
        }

        // ---- online softmax ----
        float cma = -1e30f, cmb = -1e30f;
        #pragma unroll
        for (int j = 0; j < 8; ++j) {
            cma = fmaxf(cma, fmaxf(S[j][0], S[j][1]));
            cmb = fmaxf(cmb, fmaxf(S[j][2], S[j][3]));
        }
        cma = fmaxf(cma, __shfl_xor_sync(0xffffffffu, cma, 1));
        cma = fmaxf(cma, __shfl_xor_sync(0xffffffffu, cma, 2));
        cmb = fmaxf(cmb, __shfl_xor_sync(0xffffffffu, cmb, 1));
        cmb = fmaxf(cmb, __shfl_xor_sync(0xffffffffu, cmb, 2));
        float Mna = fmaxf(Ma, cma), Mnb = fmaxf(Mb, cmb);
        float alA = __expf(Ma - Mna), alB = __expf(Mb - Mnb);
        Ma = Mna; Mb = Mnb;

        float sa = 0.f, sb = 0.f;
        #pragma unroll
        for (int j = 0; j < 8; ++j) {
            S[j][0] = __expf(S[j][0] - Ma); sa += S[j][0];
            S[j][1] = __expf(S[j][1] - Ma); sa += S[j][1];
            S[j][2] = __expf(S[j][2] - Mb); sb += S[j][2];
            S[j][3] = __expf(S[j][3] - Mb); sb += S[j][3];
        }
        sa += __shfl_xor_sync(0xffffffffu, sa, 1);
        sa += __shfl_xor_sync(0xffffffffu, sa, 2);
        sb += __shfl_xor_sync(0xffffffffu, sb, 1);
        sb += __shfl_xor_sync(0xffffffffu, sb, 2);
        la = la * alA + sa;
        lb = lb * alB + sb;
        #pragma unroll
        for (int cj = 0; cj < 8; ++cj) {
            z[cj][0] *= alA; z[cj][1] *= alA;
            z[cj][2] *= alB; z[cj][3] *= alB;
        }

        // ---- z += P @ v^T, 3-pass hi/lo; P frags direct from S regs ----
        #pragma unroll
        for (int ks = 0; ks < 4; ++ks) {
            uint4 ah = make_uint4(
                pack_bf16(S[2 * ks][0], S[2 * ks][1]),
                pack_bf16(S[2 * ks][2], S[2 * ks][3]),
                pack_bf16(S[2 * ks + 1][0], S[2 * ks + 1][1]),
                pack_bf16(S[2 * ks + 1][2], S[2 * ks + 1][3]));
            uint4 al = make_uint4(
                pack_bf16(bf16_lo(S[2 * ks][0]), bf16_lo(S[2 * ks][1])),
                pack_bf16(bf16_lo(S[2 * ks][2]), bf16_lo(S[2 * ks][3])),
                pack_bf16(bf16_lo(S[2 * ks + 1][0]), bf16_lo(S[2 * ks + 1][1])),
                pack_bf16(bf16_lo(S[2 * ks + 1][2]), bf16_lo(S[2 * ks + 1][3])));
            #pragma unroll
            for (int cj = 0; cj < 8; ++cj) {
                int c = cj * 8 + g;
                uint2 bh = make_uint2(buf[1536 + c * 36 + ks * 8 + tt],
                                      buf[1536 + c * 36 + ks * 8 + tt + 4]);
                uint2 bl = make_uint2(buf[3840 + c * 36 + ks * 8 + tt],
                                      buf[3840 + c * 36 + ks * 8 + tt + 4]);
                mma_bf16(z[cj], ah, bh);
                mma_bf16(z[cj], ah, bl);
                mma_bf16(z[cj], al, bh);
            }
        }
        asm volatile("bar.sync %0, %1;" :: "r"(1 + half), "r"(256) : "memory");
    }

    // ---- split-KV merge: half 1 publishes, half 0 combines ----
    float* zf = reinterpret_cast<float*>(pool);           // [64][128] = 8192
    float* ml = reinterpret_cast<float*>(pool + 8192);    // M[128], l[128]
    __syncthreads();
    if (half == 1) {
        #pragma unroll
        for (int cj = 0; cj < 8; ++cj) {
            int c = cj * 8 + 2 * tt;
            zf[ c      * 128 + rA    ] = z[cj][0];
            zf[(c + 1) * 128 + rA    ] = z[cj][1];
            zf[ c      * 128 + rA + 8] = z[cj][2];
            zf[(c + 1) * 128 + rA + 8] = z[cj][3];
        }
        if (tt == 0) {
            ml[rA]           = Ma;  ml[rA + 8]       = Mb;
            ml[128 + rA]     = la;  ml[128 + rA + 8] = lb;
        }
    }
    __syncthreads();
    if (half == 0) {
        float M1a = ml[rA],       l1a = ml[128 + rA];
        float M1b = ml[rA + 8],   l1b = ml[128 + rA + 8];
        float Msa = fmaxf(Ma, M1a), Msb = fmaxf(Mb, M1b);
        float w0a = __expf(Ma - Msa), w1a = __expf(M1a - Msa);
        float w0b = __expf(Mb - Msb), w1b = __expf(M1b - Msb);
        float inva = 1.f / (w0a * la + w1a * l1a);
        float invb = 1.f / (w0b * lb + w1b * l1b);
        #pragma unroll
        for (int cj = 0; cj < 8; ++cj) {
            int c = cj * 8 + 2 * tt;
            zf[ c      * 128 + rA    ] = (w0a * z[cj][0] + w1a * zf[ c      * 128 + rA    ]) * inva;
            zf[(c + 1) * 128 + rA    ] = (w0a * z[cj][1] + w1a * zf[(c + 1) * 128 + rA    ]) * inva;
            zf[ c      * 128 + rA + 8] = (w0b * z[cj][2] + w1b * zf[ c      * 128 + rA + 8]) * invb;
            zf[(c + 1) * 128 + rA + 8] = (w0b * z[cj][3] + w1b * zf[(c + 1) * 128 + rA + 8]) * invb;
        }
    }
    __syncthreads();

    // ---- z_w 1x1 epilogue (512 threads) ----
    float* zw_s = reinterpret_cast<float*>(pool + 8192);  // 4096 (ml is dead)
    for (int i = tid; i < 4096; i += 512) zw_s[i] = zw[i];
    __syncthreads();

    const int oc = tid >> 3;          // 0..63
    const int j8 = tid & 7;           // 0..7
    float4 a4[4];
    float bv = zb[oc];
    #pragma unroll
    for (int i = 0; i < 4; ++i) a4[i] = make_float4(bv, bv, bv, bv);
    #pragma unroll 8
    for (int c = 0; c < 64; ++c) {
        float wv = zw_s[oc * 64 + c];
        #pragma unroll
        for (int i = 0; i < 4; ++i) {
            float4 pv = *reinterpret_cast<const float4*>(&zf[c * 128 + j8 * 4 + 32 * i]);
            a4[i].x += wv * pv.x; a4[i].y += wv * pv.y;
            a4[i].z += wv * pv.z; a4[i].w += wv * pv.w;
        }
    }
    #pragma unroll
    for (int i = 0; i < 4; ++i) {
        int n = n0 + j8 * 4 + 32 * i;
        *reinterpret_cast<float4*>(&g_h[(b * 64 + oc) * 1024 + n]) = a4[i];
        *reinterpret_cast<float4*>(&out[((b * 64 + oc) * 16 + t) * 1024 + n]) = a4[i];
    }
}

// ---------------- orchestration --------------------------------------------
extern "C" void kernel_launch(void* const* d_in, const int* in_sizes, int n_in,
                              void* d_out, int out_size)
{
    (void)in_sizes; (void)n_in; (void)out_size;
    const float* X   = (const float*)d_in[0];
    const float* Wc  = (const float*)d_in[1];
    const float* bcc = (const float*)d_in[2];
    const float* Wci = (const float*)d_in[3];
    const float* Wcf = (const float*)d_in[4];
    const float* Wco = (const float*)d_in[5];
    const float* qw  = (const float*)d_in[6];
    const float* qb  = (const float*)d_in[7];
    const float* kw  = (const float*)d_in[8];
    const float* kb  = (const float*)d_in[9];
    const float* vw  = (const float*)d_in[10];
    const float* vb  = (const float*)d_in[11];
    const float* zw  = (const float*)d_in[12];
    const float* zb  = (const float*)d_in[13];
    float* out = (float*)d_out;

    k_init <<<4096, 256>>>();
    k_prepw<<<1152, 256>>>(Wc);
    for (int t = 0; t < NT; ++t) {
        k_conv_mma<<<dim3(8, 16, 4),  256>>>(X, t);
        k_gate    <<<4096,            256>>>(bcc, Wci, Wcf, Wco);
        k_qkv     <<<dim3(4, 12, 16), 256>>>(qw, qb, kw, kb, vw, vb);
        k_flash   <<<dim3(8, 16),     512>>>(zw, zb, out, t);
    }
}

// round 13
// speedup vs baseline: 1.3269x; 1.3269x over previous
#include <cuda_runtime.h>
#include <cuda_bf16.h>
#include <math.h>
#include <cstdint>

#define BB 16
#define NT 16

// ---------------- persistent scratch (device globals; no allocation) -------
__device__ float g_h [16*64*1024];     // attended h (recurrent carry)
__device__ float g_c [16*64*1024];     // cell state
__device__ float g_q [16*16*1024];
__device__ float g_conv[16*256*1024];  // conv output (B,256,32,32), pre-bias
// packed bf16x2 hi/lo k and v (written by k_gqkv, read by k_flash)
__device__ uint32_t g_k2h[16*1024*8];  // [b][m][c2]
__device__ uint32_t g_k2l[16*1024*8];
__device__ uint32_t g_v2h[16*64*512];  // [b][c][mp]
__device__ uint32_t g_v2l[16*64*512];
// bf16 hi/lo split conv weights in mma-fragment-linear order
__device__ uint32_t g_Wfrag[294912];
// im2col LUT: one int4 per even-k pair: {off0|flag, dydx0, off1|flag, dydx1}
__device__ int4 g_lut4[576];

// ---------------- init: zero h and c ---------------------------------------
__global__ void k_init()
{
    int i = blockIdx.x * 256 + threadIdx.x;
    g_h[i] = 0.f;
    g_c[i] = 0.f;
}

__device__ __forceinline__ float sigf(float x) { return 1.f / (1.f + __expf(-x)); }
__device__ __forceinline__ float tanh_fast(float x)
{
    return __fdividef(2.f, 1.f + __expf(-2.f * x)) - 1.f;
}
__device__ __forceinline__ uint32_t pack_bf16(float a, float b)
{
    __nv_bfloat162 h2 = __floats2bfloat162_rn(a, b);
    return *reinterpret_cast<uint32_t*>(&h2);
}
__device__ __forceinline__ float bf16_lo(float a)
{
    return a - __bfloat162float(__float2bfloat16(a));
}
__device__ __forceinline__ void mma_bf16(float* c, uint4 a, uint2 b)
{
    asm volatile(
        "mma.sync.aligned.m16n8k16.row.col.f32.bf16.bf16.f32 "
        "{%0,%1,%2,%3}, {%4,%5,%6,%7}, {%8,%9}, {%0,%1,%2,%3};"
        : "+f"(c[0]), "+f"(c[1]), "+f"(c[2]), "+f"(c[3])
        : "r"(a.x), "r"(a.y), "r"(a.z), "r"(a.w), "r"(b.x), "r"(b.y));
}

// ---------------- weight prep: split + fragment-linear layout --------------
__global__ void k_prepw(const float* __restrict__ Wc)
{
    int idx   = blockIdx.x * 256 + threadIdx.x;   // 294912
    int inner = idx & 4095;
    int outer = idx >> 12;
    int c0    = outer % 18;
    int gate  = outer / 18;
    int s     = inner & 1;
    int lane  = (inner >> 1) & 31;
    int ki    = (inner >> 6) & 3;
    int ni    = (inner >> 8) & 7;
    int sp    = (inner >> 11) & 1;

    int g = lane >> 2, tt = lane & 3;
    int n_global = gate * 64 + ni * 8 + g;
    int k0 = c0 * 64 + ki * 16 + 2 * tt + 8 * s;

    float w0, w1;
    {
        int ci = k0 / 9, r = k0 - ci * 9;
        w0 = Wc[(n_global * 128 + ci) * 9 + r];
        int k1 = k0 + 1;
        ci = k1 / 9; r = k1 - ci * 9;
        w1 = Wc[(n_global * 128 + ci) * 9 + r];
    }
    if (sp == 1) { w0 = bf16_lo(w0); w1 = bf16_lo(w1); }
    g_Wfrag[idx] = pack_bf16(w0, w1);
}

// ---------------- im2col LUT prep ------------------------------------------
__global__ void k_preplut()
{
    int p = blockIdx.x * 64 + threadIdx.x;        // 576 entries
    if (p >= 576) return;
    int4 e;
    #pragma unroll
    for (int h = 0; h < 2; ++h) {
        int kg = 2 * p + h;
        int ci = kg / 9, r = kg - ci * 9;
        int dy = r / 3 - 1, dx = r - (r / 3) * 3 - 1;
        int off = (ci < 64) ? (ci * 16384) : (((ci - 64) * 1024) | (1 << 30));
        int comp = ((dy + 8) << 16) | (dx + 8);
        if (h == 0) { e.x = off; e.y = comp; }
        else        { e.z = off; e.w = comp; }
    }
    g_lut4[p] = e;
}

// ---------------- conv via mma.sync bf16 (LUT-accelerated staging) ---------
__global__ void __launch_bounds__(256, 2) k_conv_mma(
    const float* __restrict__ X, int t)
{
    __shared__ uint32_t sm_u[12288];       // 48 KB: Ah|Al|Bh|Bl
    uint32_t* Ah_s = sm_u;
    uint32_t* Al_s = sm_u + 4096;
    uint32_t* Bh_s = sm_u + 8192;
    uint32_t* Bl_s = sm_u + 10240;

    const int tid  = threadIdx.x;
    const int wid  = tid >> 5;
    const int lane = tid & 31;
    const int mt   = blockIdx.x;
    const int b    = blockIdx.y;
    const int gate = blockIdx.z;
    const int n0   = gate * 64;
    const int wm   = wid >> 1;
    const int wn   = wid & 1;
    const int g    = lane >> 2, tt = lane & 3;

    const float* Xb = X + (b * 64 * 16 + t) * 1024;
    const float* Hb = g_h + b * 64 * 1024;

    float acc[2][4][4];
    #pragma unroll
    for (int im = 0; im < 2; ++im)
        #pragma unroll
        for (int in = 0; in < 4; ++in)
            #pragma unroll
            for (int q = 0; q < 4; ++q) acc[im][in][q] = 0.f;

    const uint4* Ah4 = reinterpret_cast<const uint4*>(Ah_s);
    const uint4* Al4 = reinterpret_cast<const uint4*>(Al_s);
    const uint2* Bh2 = reinterpret_cast<const uint2*>(Bh_s);
    const uint2* Bl2 = reinterpret_cast<const uint2*>(Bl_s);

    for (int c0 = 0; c0 < 18; ++c0) {
        // ---- stage A hi+lo via LUT ----
        #pragma unroll
        for (int j = 0; j < 16; ++j) {
            int slot = j * 256 + tid;
            int s  = slot & 3;
            int ln = (slot >> 2) & 31;
            int ki = (slot >> 7) & 3;
            int mi = slot >> 9;
            int gg = ln >> 2, t4 = ln & 3;
            int m  = mi * 16 + gg + 8 * (s & 1);
            int kb = c0 * 64 + ki * 16 + 2 * t4 + 8 * (s >> 1);
            int pix = mt * 128 + m;
            int py = pix >> 5, px = pix & 31;

            int4 e = g_lut4[kb >> 1];
            float a0 = 0.f, a1 = 0.f;
            {
                int dy = ((e.y >> 16) & 0xffff) - 8, dx = (e.y & 0xffff) - 8;
                int ys = py + dy, xs = px + dx;
                if ((unsigned)ys < 32u && (unsigned)xs < 32u) {
                    int off = e.x & 0x3fffffff;
                    const float* sp = (e.x & (1 << 30)) ? Hb : Xb;
                    a0 = sp[off + ys * 32 + xs];
                }
            }
            {
                int dy = ((e.w >> 16) & 0xffff) - 8, dx = (e.w & 0xffff) - 8;
                int ys = py + dy, xs = px + dx;
                if ((unsigned)ys < 32u && (unsigned)xs < 32u) {
                    int off = e.z & 0x3fffffff;
                    const float* sp = (e.z & (1 << 30)) ? Hb : Xb;
                    a1 = sp[off + ys * 32 + xs];
                }
            }
            Ah_s[slot] = pack_bf16(a0, a1);
            Al_s[slot] = pack_bf16(bf16_lo(a0), bf16_lo(a1));
        }
        // ---- stage Bh, Bl ----
        {
            const uint4* src = reinterpret_cast<const uint4*>(
                g_Wfrag + (gate * 18 + c0) * 4096);
            uint4* dh = reinterpret_cast<uint4*>(Bh_s);
            uint4* dl = reinterpret_cast<uint4*>(Bl_s);
            dh[tid]       = src[tid];
            dh[tid + 256] = src[tid + 256];
            dl[tid]       = src[tid + 512];
            dl[tid + 256] = src[tid + 768];
        }
        __syncthreads();

        #pragma unroll
        for (int ki = 0; ki < 4; ++ki) {
            uint4 a0h = Ah4[((wm * 2    ) * 4 + ki) * 32 + lane];
            uint4 a1h = Ah4[((wm * 2 + 1) * 4 + ki) * 32 + lane];
            uint4 a0l = Al4[((wm * 2    ) * 4 + ki) * 32 + lane];
            uint4 a1l = Al4[((wm * 2 + 1) * 4 + ki) * 32 + lane];
            #pragma unroll
            for (int in = 0; in < 4; ++in) {
                int ni = wn * 4 + in;
                uint2 bh = Bh2[(ni * 4 + ki) * 32 + lane];
                uint2 bl = Bl2[(ni * 4 + ki) * 32 + lane];
                mma_bf16(acc[0][in], a0h, bh);
                mma_bf16(acc[1][in], a1h, bh);
                mma_bf16(acc[0][in], a0h, bl);
                mma_bf16(acc[1][in], a1h, bl);
                mma_bf16(acc[0][in], a0l, bh);
                mma_bf16(acc[1][in], a1l, bh);
            }
        }
        __syncthreads();
    }

    float* out_s = reinterpret_cast<float*>(sm_u);
    #pragma unroll
    for (int im = 0; im < 2; ++im) {
        int mi = wm * 2 + im;
        int m  = mi * 16 + g;
        #pragma unroll
        for (int in = 0; in < 4; ++in) {
            int ni = wn * 4 + in;
            int n  = ni * 8 + 2 * tt;
            out_s[ n      * 132 + m    ] = acc[im][in][0];
            out_s[(n + 1) * 132 + m    ] = acc[im][in][1];
            out_s[ n      * 132 + m + 8] = acc[im][in][2];
            out_s[(n + 1) * 132 + m + 8] = acc[im][in][3];
        }
    }
    __syncthreads();
    #pragma unroll
    for (int j = 0; j < 32; ++j) {
        int idx = j * 256 + tid;
        int n = idx >> 7, m = idx & 127;
        g_conv[(b * 256 + n0 + n) * 1024 + mt * 128 + m] = out_s[n * 132 + m];
    }
}

// ---------------- fused gate + qkv -----------------------------------------
// grid (8 pos-tiles of 128, 16 b), 512 threads.
// Gate: 32-channel chunks -> h into smem (g_hg eliminated).
// QKV: thread = (pos, oc-quarter of 24); k/v emitted pre-packed bf16 hi/lo.
__global__ void __launch_bounds__(512) k_gqkv(
    const float* __restrict__ bc,
    const float* __restrict__ Wci, const float* __restrict__ Wcf,
    const float* __restrict__ Wco,
    const float* __restrict__ qw,  const float* __restrict__ qb,
    const float* __restrict__ kw,  const float* __restrict__ kb,
    const float* __restrict__ vw,  const float* __restrict__ vb)
{
    __shared__ float h_s[32 * 128];    // 16 KB
    __shared__ float w_s[96 * 33];     // 12.7 KB

    const int pt   = blockIdx.x;
    const int b    = blockIdx.y;
    const int tid  = threadIdx.x;
    const int pos  = tid >> 2;         // 0..127
    const int och  = tid & 3;          // oc quarter
    const int posg = pt * 128 + pos;

    float acc[24];
    #pragma unroll
    for (int j = 0; j < 24; ++j) {
        int oc = och * 24 + j;
        acc[j] = (oc < 16) ? qb[oc] : (oc < 32) ? kb[oc - 16] : vb[oc - 32];
    }

    for (int ch = 0; ch < 2; ++ch) {
        // stage weights w_s[oc][c_local]
        for (int i = tid; i < 3072; i += 512) {
            int oc = i >> 5, c = i & 31;
            int cg = ch * 32 + c;
            float wv = (oc < 16) ? qw[oc * 64 + cg]
                     : (oc < 32) ? kw[(oc - 16) * 64 + cg]
                                 : vw[(oc - 32) * 64 + cg];
            w_s[oc * 33 + c] = wv;
        }
        // gate for channels [ch*32, ch*32+32) x 128 pos
        #pragma unroll
        for (int r = 0; r < 8; ++r) {
            int i = tid + r * 512;            // 0..4095
            int c = i >> 7, p = i & 127;
            int cg = ch * 32 + c;
            int pg = pt * 128 + p;
            int idx = (b * 64 + cg) * 1024 + pg;
            int cb  = (b * 256 + cg) * 1024 + pg;
            float ic = g_conv[cb]              + bc[cg];
            float fc = g_conv[cb + 64 * 1024]  + bc[64 + cg];
            float gc = g_conv[cb + 128 * 1024] + bc[128 + cg];
            float oc = g_conv[cb + 192 * 1024] + bc[192 + cg];
            float cp = g_c[idx];
            int   wp = cg * 1024 + pg;
            float ii = sigf(ic + Wci[wp] * cp);
            float ff = sigf(fc + Wcf[wp] * cp);
            float nc = ff * cp + ii * tanh_fast(gc);
            float oo = sigf(oc + Wco[wp] * nc);
            g_c[idx] = nc;
            h_s[c * 128 + p] = oo * tanh_fast(nc);
        }
        __syncthreads();
        // accumulate qkv
        #pragma unroll 8
        for (int c = 0; c < 32; ++c) {
            float hv = h_s[c * 128 + pos];
            #pragma unroll
            for (int j = 0; j < 24; ++j)
                acc[j] += w_s[(och * 24 + j) * 33 + c] * hv;
        }
        __syncthreads();
    }

    // ---- outputs ----
    // q: och 0, j 0..15
    if (och == 0) {
        #pragma unroll
        for (int j = 0; j < 16; ++j)
            g_q[(b * 16 + j) * 1024 + posg] = acc[j];
    }
    // k: oc 16..31 (och0 j16..23, och1 j0..7), consecutive pairs in-thread
    #pragma unroll
    for (int j = 0; j < 24; j += 2) {
        int oc = och * 24 + j;
        if (oc >= 16 && oc < 32) {
            int c2 = (oc - 16) >> 1;
            int o  = (b * 1024 + posg) * 8 + c2;
            g_k2h[o] = pack_bf16(acc[j], acc[j + 1]);
            g_k2l[o] = pack_bf16(bf16_lo(acc[j]), bf16_lo(acc[j + 1]));
        }
    }
    // v: oc >= 32 -> vc = oc-32; pos pairs via shfl with tid^4 (pos^1)
    #pragma unroll
    for (int j = 0; j < 24; ++j) {
        int oc = och * 24 + j;
        float other = __shfl_xor_sync(0xffffffffu, acc[j], 4);
        if (oc >= 32 && ((pos & 1) == 0)) {
            int vc = oc - 32;
            int o  = (b * 64 + vc) * 512 + (posg >> 1);
            g_v2h[o] = pack_bf16(acc[j], other);
            g_v2l[o] = pack_bf16(bf16_lo(acc[j]), bf16_lo(other));
        }
    }
}

// ---------------- flash attention (R11 winner, unchanged) ------------------
// grid (8 n-tiles of 128 rows, 16 batch), 256 threads = 8 warps.
__global__ void __launch_bounds__(256) k_flash(
    const float* __restrict__ zw, const float* __restrict__ zb,
    float* __restrict__ out, int t)
{
    __shared__ uint32_t pool[12288];               // 48 KB

    const int b    = blockIdx.y;
    const int n0   = blockIdx.x * 128;
    const int tid  = threadIdx.x;
    const int w    = tid >> 5;
    const int lane = tid & 31;
    const int g    = lane >> 2, tt = lane & 3;
    const int rA   = w * 16 + g;

    float* q_s = reinterpret_cast<float*>(pool + 6144);   // [128][17]
    for (int i = tid; i < 2048; i += 256) {
        int c = i >> 7, r = i & 127;
        q_s[r * 17 + c] = g_q[(b * 16 + c) * 1024 + n0 + r];
    }
    __syncthreads();
    uint4 qh, ql;
    {
        float x0 = q_s[rA * 17 + 2 * tt],           x1 = q_s[rA * 17 + 2 * tt + 1];
        float x2 = q_s[(rA + 8) * 17 + 2 * tt],     x3 = q_s[(rA + 8) * 17 + 2 * tt + 1];
        float x4 = q_s[rA * 17 + 8 + 2 * tt],       x5 = q_s[rA * 17 + 9 + 2 * tt];
        float x6 = q_s[(rA + 8) * 17 + 8 + 2 * tt], x7 = q_s[(rA + 8) * 17 + 9 + 2 * tt];
        qh = make_uint4(pack_bf16(x0, x1), pack_bf16(x2, x3),
                        pack_bf16(x4, x5), pack_bf16(x6, x7));
        ql = make_uint4(pack_bf16(bf16_lo(x0), bf16_lo(x1)),
                        pack_bf16(bf16_lo(x2), bf16_lo(x3)),
                        pack_bf16(bf16_lo(x4), bf16_lo(x5)),
                        pack_bf16(bf16_lo(x6), bf16_lo(x7)));
    }

    uint32_t kh[2], kl[2], vh[8], vl[8];
    auto load_chunk = [&](int mc) {
        int kg = (b * 1024 + mc * 64) * 8;
        #pragma unroll
        for (int r = 0; r < 2; ++r) {
            kh[r] = g_k2h[kg + tid + r * 256];
            kl[r] = g_k2l[kg + tid + r * 256];
        }
        int vg = b * 64 * 512 + mc * 32;
        #pragma unroll
        for (int r = 0; r < 8; ++r) {
            int i = tid + r * 256;
            int c = i >> 5, mp = i & 31;
            vh[r] = g_v2h[vg + c * 512 + mp];
            vl[r] = g_v2l[vg + c * 512 + mp];
        }
    };
    auto store_chunk = [&](uint32_t* buf) {
        #pragma unroll
        for (int r = 0; r < 2; ++r) {
            int i = tid + r * 256;
            int m = i >> 3, c2 = i & 7;
            buf[m * 12 + c2]       = kh[r];
            buf[768 + m * 12 + c2] = kl[r];
        }
        #pragma unroll
        for (int r = 0; r < 8; ++r) {
            int i = tid + r * 256;
            int c = i >> 5, mp = i & 31;
            buf[1536 + c * 36 + mp] = vh[r];
            buf[3840 + c * 36 + mp] = vl[r];
        }
    };

    float z[8][4];
    #pragma unroll
    for (int cj = 0; cj < 8; ++cj)
        #pragma unroll
        for (int q = 0; q < 4; ++q) z[cj][q] = 0.f;
    float Ma = -1e30f, Mb = -1e30f, la = 0.f, lb = 0.f;

    load_chunk(0);
    store_chunk(pool);
    __syncthreads();

    for (int mch = 0; mch < 16; ++mch) {
        uint32_t* cur = pool + (mch & 1) * 6144;
        uint32_t* nxt = pool + ((mch + 1) & 1) * 6144;
        if (mch < 15) load_chunk(mch + 1);

        float S[8][4];
        #pragma unroll
        for (int j = 0; j < 8; ++j)
            #pragma unroll
            for (int q = 0; q < 4; ++q) S[j][q] = 0.f;
        #pragma unroll
        for (int j = 0; j < 8; ++j) {
            int m = j * 8 + g;
            uint2 bh = make_uint2(cur[m * 12 + tt],       cur[m * 12 + tt + 4]);
            uint2 bl = make_uint2(cur[768 + m * 12 + tt], cur[768 + m * 12 + tt + 4]);
            mma_bf16(S[j], qh, bh);
            mma_bf16(S[j], qh, bl);
            mma_bf16(S[j], ql, bh);
        }

        float cma = -1e30f, cmb = -1e30f;
        #pragma unroll
        for (int j = 0; j < 8; ++j) {
            cma = fmaxf(cma, fmaxf(S[j][0], S[j][1]));
            cmb = fmaxf(cmb, fmaxf(S[j][2], S[j][3]));
        }
        cma = fmaxf(cma, __shfl_xor_sync(0xffffffffu, cma, 1));
        cma = fmaxf(cma, __shfl_xor_sync(0xffffffffu, cma, 2));
        cmb = fmaxf(cmb, __shfl_xor_sync(0xffffffffu, cmb, 1));
        cmb = fmaxf(cmb, __shfl_xor_sync(0xffffffffu, cmb, 2));
        float Mna = fmaxf(Ma, cma), Mnb = fmaxf(Mb, cmb);
        float alA = __expf(Ma - Mna), alB = __expf(Mb - Mnb);
        Ma = Mna; Mb = Mnb;

        float sa = 0.f, sb = 0.f;
        #pragma unroll
        for (int j = 0; j < 8; ++j) {
            S[j][0] = __expf(S[j][0] - Ma); sa += S[j][0];
            S[j][1] = __expf(S[j][1] - Ma); sa += S[j][1];
            S[j][2] = __expf(S[j][2] - Mb); sb += S[j][2];
            S[j][3] = __expf(S[j][3] - Mb); sb += S[j][3];
        }
        sa += __shfl_xor_sync(0xffffffffu, sa, 1);
        sa += __shfl_xor_sync(0xffffffffu, sa, 2);
        sb += __shfl_xor_sync(0xffffffffu, sb, 1);
        sb += __shfl_xor_sync(0xffffffffu, sb, 2);
        la = la * alA + sa;
        lb = lb * alB + sb;
        #pragma unroll
        for (int cj = 0; cj < 8; ++cj) {
            z[cj][0] *= alA; z[cj][1] *= alA;
            z[cj][2] *= alB; z[cj][3] *= alB;
        }

        #pragma unroll
        for (int ks = 0; ks < 4; ++ks) {
            uint4 ah = make_uint4(
                pack_bf16(S[2 * ks][0], S[2 * ks][1]),
                pack_bf16(S[2 * ks][2], S[2 * ks][3]),
                pack_bf16(S[2 * ks + 1][0], S[2 * ks + 1][1]),
                pack_bf16(S[2 * ks + 1][2], S[2 * ks + 1][3]));
            uint4 al = make_uint4(
                pack_bf16(bf16_lo(S[2 * ks][0]), bf16_lo(S[2 * ks][1])),
                pack_bf16(bf16_lo(S[2 * ks][2]), bf16_lo(S[2 * ks][3])),
                pack_bf16(bf16_lo(S[2 * ks + 1][0]), bf16_lo(S[2 * ks + 1][1])),
                pack_bf16(bf16_lo(S[2 * ks + 1][2]), bf16_lo(S[2 * ks + 1][3])));
            #pragma unroll
            for (int cj = 0; cj < 8; ++cj) {
                int c = cj * 8 + g;
                uint2 bh = make_uint2(cur[1536 + c * 36 + ks * 8 + tt],
                                      cur[1536 + c * 36 + ks * 8 + tt + 4]);
                uint2 bl = make_uint2(cur[3840 + c * 36 + ks * 8 + tt],
                                      cur[3840 + c * 36 + ks * 8 + tt + 4]);
                mma_bf16(z[cj], ah, bh);
                mma_bf16(z[cj], ah, bl);
                mma_bf16(z[cj], al, bh);
            }
        }

        if (mch < 15) store_chunk(nxt);
        __syncthreads();
    }

    float* z_s  = reinterpret_cast<float*>(pool);          // [64][128]
    float* zw_s = reinterpret_cast<float*>(pool + 8192);   // 4096
    float lia = 1.f / la, lib = 1.f / lb;
    #pragma unroll
    for (int cj = 0; cj < 8; ++cj) {
        int c = cj * 8 + 2 * tt;
        z_s[ c      * 128 + w * 16 + g    ] = z[cj][0] * lia;
        z_s[(c + 1) * 128 + w * 16 + g    ] = z[cj][1] * lia;
        z_s[ c      * 128 + w * 16 + g + 8] = z[cj][2] * lib;
        z_s[(c + 1) * 128 + w * 16 + g + 8] = z[cj][3] * lib;
    }
    for (int i = tid; i < 4096; i += 256) zw_s[i] = zw[i];
    __syncthreads();

    const int l = lane;
    float acc2[8][4];
    #pragma unroll
    for (int ci = 0; ci < 8; ++ci) {
        float bv = zb[w * 8 + ci];
        #pragma unroll
        for (int i = 0; i < 4; ++i) acc2[ci][i] = bv;
    }
    #pragma unroll 8
    for (int c = 0; c < 64; ++c) {
        float pv[4];
        #pragma unroll
        for (int i = 0; i < 4; ++i) pv[i] = z_s[c * 128 + l + 32 * i];
        #pragma unroll
        for (int ci = 0; ci < 8; ++ci) {
            float wv = zw_s[(w * 8 + ci) * 64 + c];
            #pragma unroll
            for (int i = 0; i < 4; ++i) acc2[ci][i] += wv * pv[i];
        }
    }
    #pragma unroll
    for (int ci = 0; ci < 8; ++ci) {
        int oc = w * 8 + ci;
        #pragma unroll
        for (int i = 0; i < 4; ++i) {
            int n = n0 + l + 32 * i;
            float val = acc2[ci][i];
            g_h[(b * 64 + oc) * 1024 + n] = val;
            out[((b * 64 + oc) * 16 + t) * 1024 + n] = val;
        }
    }
}

// ---------------- orchestration --------------------------------------------
extern "C" void kernel_launch(void* const* d_in, const int* in_sizes, int n_in,
                              void* d_out, int out_size)
{
    (void)in_sizes; (void)n_in; (void)out_size;
    const float* X   = (const float*)d_in[0];
    const float* Wc  = (const float*)d_in[1];
    const float* bcc = (const float*)d_in[2];
    const float* Wci = (const float*)d_in[3];
    const float* Wcf = (const float*)d_in[4];
    const float* Wco = (const float*)d_in[5];
    const float* qw  = (const float*)d_in[6];
    const float* qb  = (const float*)d_in[7];
    const float* kw  = (const float*)d_in[8];
    const float* kb  = (const float*)d_in[9];
    const float* vw  = (const float*)d_in[10];
    const float* vb  = (const float*)d_in[11];
    const float* zw  = (const float*)d_in[12];
    const float* zb  = (const float*)d_in[13];
    float* out = (float*)d_out;

    k_init   <<<4096, 256>>>();
    k_prepw  <<<1152, 256>>>(Wc);
    k_preplut<<<9, 64>>>();
    for (int t = 0; t < NT; ++t) {
        k_conv_mma<<<dim3(8, 16, 4), 256>>>(X, t);
        k_gqkv    <<<dim3(8, 16),    512>>>(bcc, Wci, Wcf, Wco,
                                            qw, qb, kw, kb, vw, vb);
        k_flash   <<<dim3(8, 16),    256>>>(zw, zb, out, t);
    }
}

// round 14
// speedup vs baseline: 1.4834x; 1.1179x over previous
#include <cuda_runtime.h>
#include <cuda_bf16.h>
#include <math.h>
#include <cstdint>

#define BB 16
#define NT 16

// ---------------- persistent scratch (device globals; no allocation) -------
__device__ float g_h [16*64*1024];     // attended h (recurrent carry)
__device__ float g_c [16*64*1024];     // cell state
__device__ float g_q [16*16*1024];
__device__ float g_conv[16*256*1024];  // conv output (B,256,32,32), pre-bias
// packed bf16x2 hi/lo k and v (written by k_gqkv, read by k_flash)
__device__ uint32_t g_k2h[16*1024*8];  // [b][m][c2]
__device__ uint32_t g_k2l[16*1024*8];
__device__ uint32_t g_v2h[16*64*512];  // [b][c][mp]
__device__ uint32_t g_v2l[16*64*512];
// bf16 hi/lo split conv weights in mma-fragment-linear order
__device__ uint32_t g_Wfrag[294912];
// im2col LUT: one int4 per even-k pair: {off0|flag, dydx0, off1|flag, dydx1}
__device__ int4 g_lut4[576];

// ---------------- init: zero h and c ---------------------------------------
__global__ void k_init()
{
    int i = blockIdx.x * 256 + threadIdx.x;
    g_h[i] = 0.f;
    g_c[i] = 0.f;
}

__device__ __forceinline__ float sigf(float x) { return 1.f / (1.f + __expf(-x)); }
__device__ __forceinline__ float tanh_fast(float x)
{
    return __fdividef(2.f, 1.f + __expf(-2.f * x)) - 1.f;
}
__device__ __forceinline__ uint32_t pack_bf16(float a, float b)
{
    __nv_bfloat162 h2 = __floats2bfloat162_rn(a, b);
    return *reinterpret_cast<uint32_t*>(&h2);
}
__device__ __forceinline__ float bf16_lo(float a)
{
    return a - __bfloat162float(__float2bfloat16(a));
}
__device__ __forceinline__ void mma_bf16(float* c, uint4 a, uint2 b)
{
    asm volatile(
        "mma.sync.aligned.m16n8k16.row.col.f32.bf16.bf16.f32 "
        "{%0,%1,%2,%3}, {%4,%5,%6,%7}, {%8,%9}, {%0,%1,%2,%3};"
        : "+f"(c[0]), "+f"(c[1]), "+f"(c[2]), "+f"(c[3])
        : "r"(a.x), "r"(a.y), "r"(a.z), "r"(a.w), "r"(b.x), "r"(b.y));
}

// ---------------- weight prep: split + fragment-linear layout --------------
__global__ void k_prepw(const float* __restrict__ Wc)
{
    int idx   = blockIdx.x * 256 + threadIdx.x;   // 294912
    int inner = idx & 4095;
    int outer = idx >> 12;
    int c0    = outer % 18;
    int gate  = outer / 18;
    int s     = inner & 1;
    int lane  = (inner >> 1) & 31;
    int ki    = (inner >> 6) & 3;
    int ni    = (inner >> 8) & 7;
    int sp    = (inner >> 11) & 1;

    int g = lane >> 2, tt = lane & 3;
    int n_global = gate * 64 + ni * 8 + g;
    int k0 = c0 * 64 + ki * 16 + 2 * tt + 8 * s;

    float w0, w1;
    {
        int ci = k0 / 9, r = k0 - ci * 9;
        w0 = Wc[(n_global * 128 + ci) * 9 + r];
        int k1 = k0 + 1;
        ci = k1 / 9; r = k1 - ci * 9;
        w1 = Wc[(n_global * 128 + ci) * 9 + r];
    }
    if (sp == 1) { w0 = bf16_lo(w0); w1 = bf16_lo(w1); }
    g_Wfrag[idx] = pack_bf16(w0, w1);
}

// ---------------- im2col LUT prep ------------------------------------------
__global__ void k_preplut()
{
    int p = blockIdx.x * 64 + threadIdx.x;        // 576 entries
    if (p >= 576) return;
    int4 e;
    #pragma unroll
    for (int h = 0; h < 2; ++h) {
        int kg = 2 * p + h;
        int ci = kg / 9, r = kg - ci * 9;
        int dy = r / 3 - 1, dx = r - (r / 3) * 3 - 1;
        int off = (ci < 64) ? (ci * 16384) : (((ci - 64) * 1024) | (1 << 30));
        int comp = ((dy + 8) << 16) | (dx + 8);
        if (h == 0) { e.x = off; e.y = comp; }
        else        { e.z = off; e.w = comp; }
    }
    g_lut4[p] = e;
}

// ---------------- conv via mma.sync bf16: 2 gates/block, A amortized -------
// grid (8 m-tiles, 16 batch, 2 gate-pairs), 512 threads = 16 warps (4m x 4n).
// Dynamic smem 64 KB: Ah(4096) | Al(4096) | Bh(4096, 2 gates) | Bl(4096).
__global__ void __launch_bounds__(512, 1) k_conv_mma(
    const float* __restrict__ X, int t)
{
    extern __shared__ uint32_t sm_u[];     // 16384 u32 = 64 KB
    uint32_t* Ah_s = sm_u;
    uint32_t* Al_s = sm_u + 4096;
    uint32_t* Bh_s = sm_u + 8192;
    uint32_t* Bl_s = sm_u + 12288;

    const int tid  = threadIdx.x;
    const int wid  = tid >> 5;
    const int lane = tid & 31;
    const int mt   = blockIdx.x;
    const int b    = blockIdx.y;
    const int gp   = blockIdx.z;           // gate pair: gates 2gp, 2gp+1
    const int wm   = wid >> 2;              // 0..3
    const int wn   = wid & 3;               // 0..3
    const int g    = lane >> 2, tt = lane & 3;

    const float* Xb = X + (b * 64 * 16 + t) * 1024;
    const float* Hb = g_h + b * 64 * 1024;

    float acc[2][4][4];
    #pragma unroll
    for (int im = 0; im < 2; ++im)
        #pragma unroll
        for (int in = 0; in < 4; ++in)
            #pragma unroll
            for (int q = 0; q < 4; ++q) acc[im][in][q] = 0.f;

    const uint4* Ah4 = reinterpret_cast<const uint4*>(Ah_s);
    const uint4* Al4 = reinterpret_cast<const uint4*>(Al_s);
    const uint2* Bh2 = reinterpret_cast<const uint2*>(Bh_s);
    const uint2* Bl2 = reinterpret_cast<const uint2*>(Bl_s);

    for (int c0 = 0; c0 < 18; ++c0) {
        // ---- stage A hi+lo via LUT (8 slots/thread) ----
        #pragma unroll
        for (int j = 0; j < 8; ++j) {
            int slot = j * 512 + tid;
            int s  = slot & 3;
            int ln = (slot >> 2) & 31;
            int ki = (slot >> 7) & 3;
            int mi = slot >> 9;
            int gg = ln >> 2, t4 = ln & 3;
            int m  = mi * 16 + gg + 8 * (s & 1);
            int kb = c0 * 64 + ki * 16 + 2 * t4 + 8 * (s >> 1);
            int pix = mt * 128 + m;
            int py = pix >> 5, px = pix & 31;

            int4 e = g_lut4[kb >> 1];
            float a0 = 0.f, a1 = 0.f;
            {
                int dy = ((e.y >> 16) & 0xffff) - 8, dx = (e.y & 0xffff) - 8;
                int ys = py + dy, xs = px + dx;
                if ((unsigned)ys < 32u && (unsigned)xs < 32u) {
                    int off = e.x & 0x3fffffff;
                    const float* sp = (e.x & (1 << 30)) ? Hb : Xb;
                    a0 = sp[off + ys * 32 + xs];
                }
            }
            {
                int dy = ((e.w >> 16) & 0xffff) - 8, dx = (e.w & 0xffff) - 8;
                int ys = py + dy, xs = px + dx;
                if ((unsigned)ys < 32u && (unsigned)xs < 32u) {
                    int off = e.z & 0x3fffffff;
                    const float* sp = (e.z & (1 << 30)) ? Hb : Xb;
                    a1 = sp[off + ys * 32 + xs];
                }
            }
            Ah_s[slot] = pack_bf16(a0, a1);
            Al_s[slot] = pack_bf16(bf16_lo(a0), bf16_lo(a1));
        }
        // ---- stage B (both gates, hi+lo): 4 uint4/thread ----
        {
            uint4* dh = reinterpret_cast<uint4*>(Bh_s);
            uint4* dl = reinterpret_cast<uint4*>(Bl_s);
            #pragma unroll
            for (int gsel = 0; gsel < 2; ++gsel) {
                const uint4* src = reinterpret_cast<const uint4*>(
                    g_Wfrag + ((2 * gp + gsel) * 18 + c0) * 4096);
                dh[gsel * 512 + tid] = src[tid];
                dl[gsel * 512 + tid] = src[tid + 512];
            }
        }
        __syncthreads();

        // ---- 3 hi/lo passes, 2 m-tiles x 4 n-tiles per warp ----
        #pragma unroll
        for (int ki = 0; ki < 4; ++ki) {
            uint4 a0h = Ah4[((wm * 2    ) * 4 + ki) * 32 + lane];
            uint4 a1h = Ah4[((wm * 2 + 1) * 4 + ki) * 32 + lane];
            uint4 a0l = Al4[((wm * 2    ) * 4 + ki) * 32 + lane];
            uint4 a1l = Al4[((wm * 2 + 1) * 4 + ki) * 32 + lane];
            #pragma unroll
            for (int in = 0; in < 4; ++in) {
                int ni   = wn * 4 + in;              // 0..15
                int bidx = (ni >> 3) * 1024 + ((ni & 7) * 4 + ki) * 32 + lane;
                uint2 bh = Bh2[bidx];
                uint2 bl = Bl2[bidx];
                mma_bf16(acc[0][in], a0h, bh);
                mma_bf16(acc[1][in], a1h, bh);
                mma_bf16(acc[0][in], a0h, bl);
                mma_bf16(acc[1][in], a1h, bl);
                mma_bf16(acc[0][in], a0l, bh);
                mma_bf16(acc[1][in], a1l, bh);
            }
        }
        __syncthreads();
    }

    // ---- epilogue: two 64-n passes through smem, coalesced writes ----
    float* out_s = reinterpret_cast<float*>(sm_u);   // 64 x 132 floats
    #pragma unroll
    for (int p = 0; p < 2; ++p) {
        __syncthreads();
        #pragma unroll
        for (int im = 0; im < 2; ++im) {
            int m = (wm * 2 + im) * 16 + g;
            #pragma unroll
            for (int in = 0; in < 4; ++in) {
                int ni = wn * 4 + in;
                if ((ni >> 3) == p) {
                    int n = (ni & 7) * 8 + 2 * tt;
                    out_s[ n      * 132 + m    ] = acc[im][in][0];
                    out_s[(n + 1) * 132 + m    ] = acc[im][in][1];
                    out_s[ n      * 132 + m + 8] = acc[im][in][2];
                    out_s[(n + 1) * 132 + m + 8] = acc[im][in][3];
                }
            }
        }
        __syncthreads();
        #pragma unroll
        for (int j = 0; j < 16; ++j) {
            int idx = j * 512 + tid;                 // 8192 = 64n x 128m
            int n = idx >> 7, m = idx & 127;
            g_conv[(b * 256 + (2 * gp + p) * 64 + n) * 1024 + mt * 128 + m]
                = out_s[n * 132 + m];
        }
    }
}

// ---------------- fused gate + qkv (R13 winner, unchanged) -----------------
__global__ void __launch_bounds__(512) k_gqkv(
    const float* __restrict__ bc,
    const float* __restrict__ Wci, const float* __restrict__ Wcf,
    const float* __restrict__ Wco,
    const float* __restrict__ qw,  const float* __restrict__ qb,
    const float* __restrict__ kw,  const float* __restrict__ kb,
    const float* __restrict__ vw,  const float* __restrict__ vb)
{
    __shared__ float h_s[32 * 128];    // 16 KB
    __shared__ float w_s[96 * 33];     // 12.7 KB

    const int pt   = blockIdx.x;
    const int b    = blockIdx.y;
    const int tid  = threadIdx.x;
    const int pos  = tid >> 2;
    const int och  = tid & 3;
    const int posg = pt * 128 + pos;

    float acc[24];
    #pragma unroll
    for (int j = 0; j < 24; ++j) {
        int oc = och * 24 + j;
        acc[j] = (oc < 16) ? qb[oc] : (oc < 32) ? kb[oc - 16] : vb[oc - 32];
    }

    for (int ch = 0; ch < 2; ++ch) {
        for (int i = tid; i < 3072; i += 512) {
            int oc = i >> 5, c = i & 31;
            int cg = ch * 32 + c;
            float wv = (oc < 16) ? qw[oc * 64 + cg]
                     : (oc < 32) ? kw[(oc - 16) * 64 + cg]
                                 : vw[(oc - 32) * 64 + cg];
            w_s[oc * 33 + c] = wv;
        }
        #pragma unroll
        for (int r = 0; r < 8; ++r) {
            int i = tid + r * 512;
            int c = i >> 7, p = i & 127;
            int cg = ch * 32 + c;
            int pg = pt * 128 + p;
            int idx = (b * 64 + cg) * 1024 + pg;
            int cb  = (b * 256 + cg) * 1024 + pg;
            float ic = g_conv[cb]              + bc[cg];
            float fc = g_conv[cb + 64 * 1024]  + bc[64 + cg];
            float gc = g_conv[cb + 128 * 1024] + bc[128 + cg];
            float oc = g_conv[cb + 192 * 1024] + bc[192 + cg];
            float cp = g_c[idx];
            int   wp = cg * 1024 + pg;
            float ii = sigf(ic + Wci[wp] * cp);
            float ff = sigf(fc + Wcf[wp] * cp);
            float nc = ff * cp + ii * tanh_fast(gc);
            float oo = sigf(oc + Wco[wp] * nc);
            g_c[idx] = nc;
            h_s[c * 128 + p] = oo * tanh_fast(nc);
        }
        __syncthreads();
        #pragma unroll 8
        for (int c = 0; c < 32; ++c) {
            float hv = h_s[c * 128 + pos];
            #pragma unroll
            for (int j = 0; j < 24; ++j)
                acc[j] += w_s[(och * 24 + j) * 33 + c] * hv;
        }
        __syncthreads();
    }

    if (och == 0) {
        #pragma unroll
        for (int j = 0; j < 16; ++j)
            g_q[(b * 16 + j) * 1024 + posg] = acc[j];
    }
    #pragma unroll
    for (int j = 0; j < 24; j += 2) {
        int oc = och * 24 + j;
        if (oc >= 16 && oc < 32) {
            int c2 = (oc - 16) >> 1;
            int o  = (b * 1024 + posg) * 8 + c2;
            g_k2h[o] = pack_bf16(acc[j], acc[j + 1]);
            g_k2l[o] = pack_bf16(bf16_lo(acc[j]), bf16_lo(acc[j + 1]));
        }
    }
    #pragma unroll
    for (int j = 0; j < 24; ++j) {
        int oc = och * 24 + j;
        float other = __shfl_xor_sync(0xffffffffu, acc[j], 4);
        if (oc >= 32 && ((pos & 1) == 0)) {
            int vc = oc - 32;
            int o  = (b * 64 + vc) * 512 + (posg >> 1);
            g_v2h[o] = pack_bf16(acc[j], other);
            g_v2l[o] = pack_bf16(bf16_lo(acc[j]), bf16_lo(other));
        }
    }
}

// ---------------- flash attention (R11/R13 winner, unchanged) --------------
__global__ void __launch_bounds__(256) k_flash(
    const float* __restrict__ zw, const float* __restrict__ zb,
    float* __restrict__ out, int t)
{
    __shared__ uint32_t pool[12288];               // 48 KB

    const int b    = blockIdx.y;
    const int n0   = blockIdx.x * 128;
    const int tid  = threadIdx.x;
    const int w    = tid >> 5;
    const int lane = tid & 31;
    const int g    = lane >> 2, tt = lane & 3;
    const int rA   = w * 16 + g;

    float* q_s = reinterpret_cast<float*>(pool + 6144);   // [128][17]
    for (int i = tid; i < 2048; i += 256) {
        int c = i >> 7, r = i & 127;
        q_s[r * 17 + c] = g_q[(b * 16 + c) * 1024 + n0 + r];
    }
    __syncthreads();
    uint4 qh, ql;
    {
        float x0 = q_s[rA * 17 + 2 * tt],           x1 = q_s[rA * 17 + 2 * tt + 1];
        float x2 = q_s[(rA + 8) * 17 + 2 * tt],     x3 = q_s[(rA + 8) * 17 + 2 * tt + 1];
        float x4 = q_s[rA * 17 + 8 + 2 * tt],       x5 = q_s[rA * 17 + 9 + 2 * tt];
        float x6 = q_s[(rA + 8) * 17 + 8 + 2 * tt], x7 = q_s[(rA + 8) * 17 + 9 + 2 * tt];
        qh = make_uint4(pack_bf16(x0, x1), pack_bf16(x2, x3),
                        pack_bf16(x4, x5), pack_bf16(x6, x7));
        ql = make_uint4(pack_bf16(bf16_lo(x0), bf16_lo(x1)),
                        pack_bf16(bf16_lo(x2), bf16_lo(x3)),
                        pack_bf16(bf16_lo(x4), bf16_lo(x5)),
                        pack_bf16(bf16_lo(x6), bf16_lo(x7)));
    }

    uint32_t kh[2], kl[2], vh[8], vl[8];
    auto load_chunk = [&](int mc) {
        int kg = (b * 1024 + mc * 64) * 8;
        #pragma unroll
        for (int r = 0; r < 2; ++r) {
            kh[r] = g_k2h[kg + tid + r * 256];
            kl[r] = g_k2l[kg + tid + r * 256];
        }
        int vg = b * 64 * 512 + mc * 32;
        #pragma unroll
        for (int r = 0; r < 8; ++r) {
            int i = tid + r * 256;
            int c = i >> 5, mp = i & 31;
            vh[r] = g_v2h[vg + c * 512 + mp];
            vl[r] = g_v2l[vg + c * 512 + mp];
        }
    };
    auto store_chunk = [&](uint32_t* buf) {
        #pragma unroll
        for (int r = 0; r < 2; ++r) {
            int i = tid + r * 256;
            int m = i >> 3, c2 = i & 7;
            buf[m * 12 + c2]       = kh[r];
            buf[768 + m * 12 + c2] = kl[r];
        }
        #pragma unroll
        for (int r = 0; r < 8; ++r) {
            int i = tid + r * 256;
            int c = i >> 5, mp = i & 31;
            buf[1536 + c * 36 + mp] = vh[r];
            buf[3840 + c * 36 + mp] = vl[r];
        }
    };

    float z[8][4];
    #pragma unroll
    for (int cj = 0; cj < 8; ++cj)
        #pragma unroll
        for (int q = 0; q < 4; ++q) z[cj][q] = 0.f;
    float Ma = -1e30f, Mb = -1e30f, la = 0.f, lb = 0.f;

    load_chunk(0);
    store_chunk(pool);
    __syncthreads();

    for (int mch = 0; mch < 16; ++mch) {
        uint32_t* cur = pool + (mch & 1) * 6144;
        uint32_t* nxt = pool + ((mch + 1) & 1) * 6144;
        if (mch < 15) load_chunk(mch + 1);

        float S[8][4];
        #pragma unroll
        for (int j = 0; j < 8; ++j)
            #pragma unroll
            for (int q = 0; q < 4; ++q) S[j][q] = 0.f;
        #pragma unroll
        for (int j = 0; j < 8; ++j) {
            int m = j * 8 + g;
            uint2 bh = make_uint2(cur[m * 12 + tt],       cur[m * 12 + tt + 4]);
            uint2 bl = make_uint2(cur[768 + m * 12 + tt], cur[768 + m * 12 + tt + 4]);
            mma_bf16(S[j], qh, bh);
            mma_bf16(S[j], qh, bl);
            mma_bf16(S[j], ql, bh);
        }

        float cma = -1e30f, cmb = -1e30f;
        #pragma unroll
        for (int j = 0; j < 8; ++j) {
            cma = fmaxf(cma, fmaxf(S[j][0], S[j][1]));
            cmb = fmaxf(cmb, fmaxf(S[j][2], S[j][3]));
        }
        cma = fmaxf(cma, __shfl_xor_sync(0xffffffffu, cma, 1));
        cma = fmaxf(cma, __shfl_xor_sync(0xffffffffu, cma, 2));
        cmb = fmaxf(cmb, __shfl_xor_sync(0xffffffffu, cmb, 1));
        cmb = fmaxf(cmb, __shfl_xor_sync(0xffffffffu, cmb, 2));
        float Mna = fmaxf(Ma, cma), Mnb = fmaxf(Mb, cmb);
        float alA = __expf(Ma - Mna), alB = __expf(Mb - Mnb);
        Ma = Mna; Mb = Mnb;

        float sa = 0.f, sb = 0.f;
        #pragma unroll
        for (int j = 0; j < 8; ++j) {
            S[j][0] = __expf(S[j][0] - Ma); sa += S[j][0];
            S[j][1] = __expf(S[j][1] - Ma); sa += S[j][1];
            S[j][2] = __expf(S[j][2] - Mb); sb += S[j][2];
            S[j][3] = __expf(S[j][3] - Mb); sb += S[j][3];
        }
        sa += __shfl_xor_sync(0xffffffffu, sa, 1);
        sa += __shfl_xor_sync(0xffffffffu, sa, 2);
        sb += __shfl_xor_sync(0xffffffffu, sb, 1);
        sb += __shfl_xor_sync(0xffffffffu, sb, 2);
        la = la * alA + sa;
        lb = lb * alB + sb;
        #pragma unroll
        for (int cj = 0; cj < 8; ++cj) {
            z[cj][0] *= alA; z[cj][1] *= alA;
            z[cj][2] *= alB; z[cj][3] *= alB;
        }

        #pragma unroll
        for (int ks = 0; ks < 4; ++ks) {
            uint4 ah = make_uint4(
                pack_bf16(S[2 * ks][0], S[2 * ks][1]),
                pack_bf16(S[2 * ks][2], S[2 * ks][3]),
                pack_bf16(S[2 * ks + 1][0], S[2 * ks + 1][1]),
                pack_bf16(S[2 * ks + 1][2], S[2 * ks + 1][3]));
            uint4 al = make_uint4(
                pack_bf16(bf16_lo(S[2 * ks][0]), bf16_lo(S[2 * ks][1])),
                pack_bf16(bf16_lo(S[2 * ks][2]), bf16_lo(S[2 * ks][3])),
                pack_bf16(bf16_lo(S[2 * ks + 1][0]), bf16_lo(S[2 * ks + 1][1])),
                pack_bf16(bf16_lo(S[2 * ks + 1][2]), bf16_lo(S[2 * ks + 1][3])));
            #pragma unroll
            for (int cj = 0; cj < 8; ++cj) {
                int c = cj * 8 + g;
                uint2 bh = make_uint2(cur[1536 + c * 36 + ks * 8 + tt],
                                      cur[1536 + c * 36 + ks * 8 + tt + 4]);
                uint2 bl = make_uint2(cur[3840 + c * 36 + ks * 8 + tt],
                                      cur[3840 + c * 36 + ks * 8 + tt + 4]);
                mma_bf16(z[cj], ah, bh);
                mma_bf16(z[cj], ah, bl);
                mma_bf16(z[cj], al, bh);
            }
        }

        if (mch < 15) store_chunk(nxt);
        __syncthreads();
    }

    float* z_s  = reinterpret_cast<float*>(pool);          // [64][128]
    float* zw_s = reinterpret_cast<float*>(pool + 8192);   // 4096
    float lia = 1.f / la, lib = 1.f / lb;
    #pragma unroll
    for (int cj = 0; cj < 8; ++cj) {
        int c = cj * 8 + 2 * tt;
        z_s[ c      * 128 + w * 16 + g    ] = z[cj][0] * lia;
        z_s[(c + 1) * 128 + w * 16 + g    ] = z[cj][1] * lia;
        z_s[ c      * 128 + w * 16 + g + 8] = z[cj][2] * lib;
        z_s[(c + 1) * 128 + w * 16 + g + 8] = z[cj][3] * lib;
    }
    for (int i = tid; i < 4096; i += 256) zw_s[i] = zw[i];
    __syncthreads();

    const int l = lane;
    float acc2[8][4];
    #pragma unroll
    for (int ci = 0; ci < 8; ++ci) {
        float bv = zb[w * 8 + ci];
        #pragma unroll
        for (int i = 0; i < 4; ++i) acc2[ci][i] = bv;
    }
    #pragma unroll 8
    for (int c = 0; c < 64; ++c) {
        float pv[4];
        #pragma unroll
        for (int i = 0; i < 4; ++i) pv[i] = z_s[c * 128 + l + 32 * i];
        #pragma unroll
        for (int ci = 0; ci < 8; ++ci) {
            float wv = zw_s[(w * 8 + ci) * 64 + c];
            #pragma unroll
            for (int i = 0; i < 4; ++i) acc2[ci][i] += wv * pv[i];
        }
    }
    #pragma unroll
    for (int ci = 0; ci < 8; ++ci) {
        int oc = w * 8 + ci;
        #pragma unroll
        for (int i = 0; i < 4; ++i) {
            int n = n0 + l + 32 * i;
            float val = acc2[ci][i];
            g_h[(b * 64 + oc) * 1024 + n] = val;
            out[((b * 64 + oc) * 16 + t) * 1024 + n] = val;
        }
    }
}

// ---------------- orchestration --------------------------------------------
extern "C" void kernel_launch(void* const* d_in, const int* in_sizes, int n_in,
                              void* d_out, int out_size)
{
    (void)in_sizes; (void)n_in; (void)out_size;
    const float* X   = (const float*)d_in[0];
    const float* Wc  = (const float*)d_in[1];
    const float* bcc = (const float*)d_in[2];
    const float* Wci = (const float*)d_in[3];
    const float* Wcf = (const float*)d_in[4];
    const float* Wco = (const float*)d_in[5];
    const float* qw  = (const float*)d_in[6];
    const float* qb  = (const float*)d_in[7];
    const float* kw  = (const float*)d_in[8];
    const float* kb  = (const float*)d_in[9];
    const float* vw  = (const float*)d_in[10];
    const float* vb  = (const float*)d_in[11];
    const float* zw  = (const float*)d_in[12];
    const float* zb  = (const float*)d_in[13];
    float* out = (float*)d_out;

    cudaFuncSetAttribute(k_conv_mma,
                         cudaFuncAttributeMaxDynamicSharedMemorySize, 65536);

    k_init   <<<4096, 256>>>();
    k_prepw  <<<1152, 256>>>(Wc);
    k_preplut<<<9, 64>>>();
    for (int t = 0; t < NT; ++t) {
        k_conv_mma<<<dim3(8, 16, 2), 512, 65536>>>(X, t);
        k_gqkv    <<<dim3(8, 16),    512>>>(bcc, Wci, Wcf, Wco,
                                            qw, qb, kw, kb, vw, vb);
        k_flash   <<<dim3(8, 16),    256>>>(zw, zb, out, t);
    }
}

// round 15
// speedup vs baseline: 1.4992x; 1.0107x over previous
#include <cuda_runtime.h>
#include <cuda_bf16.h>
#include <math.h>
#include <cstdint>

#define BB 16
#define NT 16

// ---------------- persistent scratch (device globals; no allocation) -------
__device__ float g_h [16*64*1024];     // attended h (recurrent carry)
__device__ float g_c [16*64*1024];     // cell state
__device__ float g_q [16*16*1024];
__device__ float g_conv[16*256*1024];  // conv output (B,256,32,32), pre-bias
// packed bf16x2 hi/lo k and v (written by k_gqkv, read by k_flash)
__device__ uint32_t g_k2h[16*1024*8];  // [b][m][c2]
__device__ uint32_t g_k2l[16*1024*8];
__device__ uint32_t g_v2h[16*64*512];  // [b][c][mp]
__device__ uint32_t g_v2l[16*64*512];
// bf16 hi/lo split conv weights in mma-fragment-linear order
__device__ uint32_t g_Wfrag[294912];
// im2col LUT: one int4 per even-k pair: {off0|flag, dydx0, off1|flag, dydx1}
__device__ int4 g_lut4[576];

// ---------------- init: zero h and c ---------------------------------------
__global__ void k_init()
{
    int i = blockIdx.x * 256 + threadIdx.x;
    g_h[i] = 0.f;
    g_c[i] = 0.f;
}

__device__ __forceinline__ float sigf(float x) { return 1.f / (1.f + __expf(-x)); }
__device__ __forceinline__ float tanh_fast(float x)
{
    return __fdividef(2.f, 1.f + __expf(-2.f * x)) - 1.f;
}
__device__ __forceinline__ uint32_t pack_bf16(float a, float b)
{
    __nv_bfloat162 h2 = __floats2bfloat162_rn(a, b);
    return *reinterpret_cast<uint32_t*>(&h2);
}
__device__ __forceinline__ float bf16_lo(float a)
{
    return a - __bfloat162float(__float2bfloat16(a));
}
__device__ __forceinline__ void mma_bf16(float* c, uint4 a, uint2 b)
{
    asm volatile(
        "mma.sync.aligned.m16n8k16.row.col.f32.bf16.bf16.f32 "
        "{%0,%1,%2,%3}, {%4,%5,%6,%7}, {%8,%9}, {%0,%1,%2,%3};"
        : "+f"(c[0]), "+f"(c[1]), "+f"(c[2]), "+f"(c[3])
        : "r"(a.x), "r"(a.y), "r"(a.z), "r"(a.w), "r"(b.x), "r"(b.y));
}

// ---------------- weight prep: split + fragment-linear layout --------------
__global__ void k_prepw(const float* __restrict__ Wc)
{
    int idx   = blockIdx.x * 256 + threadIdx.x;   // 294912
    int inner = idx & 4095;
    int outer = idx >> 12;
    int c0    = outer % 18;
    int gate  = outer / 18;
    int s     = inner & 1;
    int lane  = (inner >> 1) & 31;
    int ki    = (inner >> 6) & 3;
    int ni    = (inner >> 8) & 7;
    int sp    = (inner >> 11) & 1;

    int g = lane >> 2, tt = lane & 3;
    int n_global = gate * 64 + ni * 8 + g;
    int k0 = c0 * 64 + ki * 16 + 2 * tt + 8 * s;

    float w0, w1;
    {
        int ci = k0 / 9, r = k0 - ci * 9;
        w0 = Wc[(n_global * 128 + ci) * 9 + r];
        int k1 = k0 + 1;
        ci = k1 / 9; r = k1 - ci * 9;
        w1 = Wc[(n_global * 128 + ci) * 9 + r];
    }
    if (sp == 1) { w0 = bf16_lo(w0); w1 = bf16_lo(w1); }
    g_Wfrag[idx] = pack_bf16(w0, w1);
}

// ---------------- im2col LUT prep ------------------------------------------
__global__ void k_preplut()
{
    int p = blockIdx.x * 64 + threadIdx.x;        // 576 entries
    if (p >= 576) return;
    int4 e;
    #pragma unroll
    for (int h = 0; h < 2; ++h) {
        int kg = 2 * p + h;
        int ci = kg / 9, r = kg - ci * 9;
        int dy = r / 3 - 1, dx = r - (r / 3) * 3 - 1;
        int off = (ci < 64) ? (ci * 16384) : (((ci - 64) * 1024) | (1 << 30));
        int comp = ((dy + 8) << 16) | (dx + 8);
        if (h == 0) { e.x = off; e.y = comp; }
        else        { e.z = off; e.w = comp; }
    }
    g_lut4[p] = e;
}

// ---------------- conv via mma.sync bf16: double-buffered pipeline ---------
// grid (8 m-tiles, 16 batch, 2 gate-pairs), 512 threads = 16 warps (4m x 4n).
// Dynamic smem 128 KB: 2 buffers x [Ah 4096 | Al 4096 | Bh 4096 | Bl 4096].
// Per chunk: stage(next) issued BEFORE mma(cur); one sync per chunk.
__global__ void __launch_bounds__(512, 1) k_conv_mma(
    const float* __restrict__ X, int t)
{
    extern __shared__ uint32_t sm_u[];     // 32768 u32 = 128 KB

    const int tid  = threadIdx.x;
    const int wid  = tid >> 5;
    const int lane = tid & 31;
    const int mt   = blockIdx.x;
    const int b    = blockIdx.y;
    const int gp   = blockIdx.z;
    const int wm   = wid >> 2;
    const int wn   = wid & 3;
    const int g    = lane >> 2, tt = lane & 3;

    const float* Xb = X + (b * 64 * 16 + t) * 1024;
    const float* Hb = g_h + b * 64 * 1024;

    float acc[2][4][4];
    #pragma unroll
    for (int im = 0; im < 2; ++im)
        #pragma unroll
        for (int in = 0; in < 4; ++in)
            #pragma unroll
            for (int q = 0; q < 4; ++q) acc[im][in][q] = 0.f;

    // ---- staging helpers ----
    auto stage = [&](uint32_t* buf, int c0) {
        uint32_t* Ah_s = buf;
        uint32_t* Al_s = buf + 4096;
        // A: 8 slots/thread via LUT
        #pragma unroll
        for (int j = 0; j < 8; ++j) {
            int slot = j * 512 + tid;
            int s  = slot & 3;
            int ln = (slot >> 2) & 31;
            int ki = (slot >> 7) & 3;
            int mi = slot >> 9;
            int gg = ln >> 2, t4 = ln & 3;
            int m  = mi * 16 + gg + 8 * (s & 1);
            int kb = c0 * 64 + ki * 16 + 2 * t4 + 8 * (s >> 1);
            int pix = mt * 128 + m;
            int py = pix >> 5, px = pix & 31;

            int4 e = g_lut4[kb >> 1];
            float a0 = 0.f, a1 = 0.f;
            {
                int dy = ((e.y >> 16) & 0xffff) - 8, dx = (e.y & 0xffff) - 8;
                int ys = py + dy, xs = px + dx;
                if ((unsigned)ys < 32u && (unsigned)xs < 32u) {
                    int off = e.x & 0x3fffffff;
                    const float* sp = (e.x & (1 << 30)) ? Hb : Xb;
                    a0 = sp[off + ys * 32 + xs];
                }
            }
            {
                int dy = ((e.w >> 16) & 0xffff) - 8, dx = (e.w & 0xffff) - 8;
                int ys = py + dy, xs = px + dx;
                if ((unsigned)ys < 32u && (unsigned)xs < 32u) {
                    int off = e.z & 0x3fffffff;
                    const float* sp = (e.z & (1 << 30)) ? Hb : Xb;
                    a1 = sp[off + ys * 32 + xs];
                }
            }
            Ah_s[slot] = pack_bf16(a0, a1);
            Al_s[slot] = pack_bf16(bf16_lo(a0), bf16_lo(a1));
        }
        // B: both gates, hi+lo, 4 uint4/thread
        uint4* dh = reinterpret_cast<uint4*>(buf + 8192);
        uint4* dl = reinterpret_cast<uint4*>(buf + 12288);
        #pragma unroll
        for (int gsel = 0; gsel < 2; ++gsel) {
            const uint4* src = reinterpret_cast<const uint4*>(
                g_Wfrag + ((2 * gp + gsel) * 18 + c0) * 4096);
            dh[gsel * 512 + tid] = src[tid];
            dl[gsel * 512 + tid] = src[tid + 512];
        }
    };

    // prologue: stage chunk 0 into buffer 0
    stage(sm_u, 0);
    __syncthreads();

    for (int c0 = 0; c0 < 18; ++c0) {
        uint32_t* cur = sm_u + (c0 & 1) * 16384;
        uint32_t* nxt = sm_u + ((c0 + 1) & 1) * 16384;

        // prefetch next chunk (LDGs issue early, hide under mma below)
        if (c0 < 17) stage(nxt, c0 + 1);

        const uint4* Ah4 = reinterpret_cast<const uint4*>(cur);
        const uint4* Al4 = reinterpret_cast<const uint4*>(cur + 4096);
        const uint2* Bh2 = reinterpret_cast<const uint2*>(cur + 8192);
        const uint2* Bl2 = reinterpret_cast<const uint2*>(cur + 12288);

        #pragma unroll
        for (int ki = 0; ki < 4; ++ki) {
            uint4 a0h = Ah4[((wm * 2    ) * 4 + ki) * 32 + lane];
            uint4 a1h = Ah4[((wm * 2 + 1) * 4 + ki) * 32 + lane];
            uint4 a0l = Al4[((wm * 2    ) * 4 + ki) * 32 + lane];
            uint4 a1l = Al4[((wm * 2 + 1) * 4 + ki) * 32 + lane];
            #pragma unroll
            for (int in = 0; in < 4; ++in) {
                int ni   = wn * 4 + in;
                int bidx = (ni >> 3) * 1024 + ((ni & 7) * 4 + ki) * 32 + lane;
                uint2 bh = Bh2[bidx];
                uint2 bl = Bl2[bidx];
                mma_bf16(acc[0][in], a0h, bh);
                mma_bf16(acc[1][in], a1h, bh);
                mma_bf16(acc[0][in], a0h, bl);
                mma_bf16(acc[1][in], a1h, bl);
                mma_bf16(acc[0][in], a0l, bh);
                mma_bf16(acc[1][in], a1l, bh);
            }
        }
        __syncthreads();
    }

    // ---- epilogue: two 64-n passes through smem, coalesced writes ----
    float* out_s = reinterpret_cast<float*>(sm_u);   // 64 x 132 floats
    #pragma unroll
    for (int p = 0; p < 2; ++p) {
        __syncthreads();
        #pragma unroll
        for (int im = 0; im < 2; ++im) {
            int m = (wm * 2 + im) * 16 + g;
            #pragma unroll
            for (int in = 0; in < 4; ++in) {
                int ni = wn * 4 + in;
                if ((ni >> 3) == p) {
                    int n = (ni & 7) * 8 + 2 * tt;
                    out_s[ n      * 132 + m    ] = acc[im][in][0];
                    out_s[(n + 1) * 132 + m    ] = acc[im][in][1];
                    out_s[ n      * 132 + m + 8] = acc[im][in][2];
                    out_s[(n + 1) * 132 + m + 8] = acc[im][in][3];
                }
            }
        }
        __syncthreads();
        #pragma unroll
        for (int j = 0; j < 16; ++j) {
            int idx = j * 512 + tid;                 // 8192 = 64n x 128m
            int n = idx >> 7, m = idx & 127;
            g_conv[(b * 256 + (2 * gp + p) * 64 + n) * 1024 + mt * 128 + m]
                = out_s[n * 132 + m];
        }
    }
}

// ---------------- fused gate + qkv (R13 winner, unchanged) -----------------
__global__ void __launch_bounds__(512) k_gqkv(
    const float* __restrict__ bc,
    const float* __restrict__ Wci, const float* __restrict__ Wcf,
    const float* __restrict__ Wco,
    const float* __restrict__ qw,  const float* __restrict__ qb,
    const float* __restrict__ kw,  const float* __restrict__ kb,
    const float* __restrict__ vw,  const float* __restrict__ vb)
{
    __shared__ float h_s[32 * 128];    // 16 KB
    __shared__ float w_s[96 * 33];     // 12.7 KB

    const int pt   = blockIdx.x;
    const int b    = blockIdx.y;
    const int tid  = threadIdx.x;
    const int pos  = tid >> 2;
    const int och  = tid & 3;
    const int posg = pt * 128 + pos;

    float acc[24];
    #pragma unroll
    for (int j = 0; j < 24; ++j) {
        int oc = och * 24 + j;
        acc[j] = (oc < 16) ? qb[oc] : (oc < 32) ? kb[oc - 16] : vb[oc - 32];
    }

    for (int ch = 0; ch < 2; ++ch) {
        for (int i = tid; i < 3072; i += 512) {
            int oc = i >> 5, c = i & 31;
            int cg = ch * 32 + c;
            float wv = (oc < 16) ? qw[oc * 64 + cg]
                     : (oc < 32) ? kw[(oc - 16) * 64 + cg]
                                 : vw[(oc - 32) * 64 + cg];
            w_s[oc * 33 + c] = wv;
        }
        #pragma unroll
        for (int r = 0; r < 8; ++r) {
            int i = tid + r * 512;
            int c = i >> 7, p = i & 127;
            int cg = ch * 32 + c;
            int pg = pt * 128 + p;
            int idx = (b * 64 + cg) * 1024 + pg;
            int cb  = (b * 256 + cg) * 1024 + pg;
            float ic = g_conv[cb]              + bc[cg];
            float fc = g_conv[cb + 64 * 1024]  + bc[64 + cg];
            float gc = g_conv[cb + 128 * 1024] + bc[128 + cg];
            float oc = g_conv[cb + 192 * 1024] + bc[192 + cg];
            float cp = g_c[idx];
            int   wp = cg * 1024 + pg;
            float ii = sigf(ic + Wci[wp] * cp);
            float ff = sigf(fc + Wcf[wp] * cp);
            float nc = ff * cp + ii * tanh_fast(gc);
            float oo = sigf(oc + Wco[wp] * nc);
            g_c[idx] = nc;
            h_s[c * 128 + p] = oo * tanh_fast(nc);
        }
        __syncthreads();
        #pragma unroll 8
        for (int c = 0; c < 32; ++c) {
            float hv = h_s[c * 128 + pos];
            #pragma unroll
            for (int j = 0; j < 24; ++j)
                acc[j] += w_s[(och * 24 + j) * 33 + c] * hv;
        }
        __syncthreads();
    }

    if (och == 0) {
        #pragma unroll
        for (int j = 0; j < 16; ++j)
            g_q[(b * 16 + j) * 1024 + posg] = acc[j];
    }
    #pragma unroll
    for (int j = 0; j < 24; j += 2) {
        int oc = och * 24 + j;
        if (oc >= 16 && oc < 32) {
            int c2 = (oc - 16) >> 1;
            int o  = (b * 1024 + posg) * 8 + c2;
            g_k2h[o] = pack_bf16(acc[j], acc[j + 1]);
            g_k2l[o] = pack_bf16(bf16_lo(acc[j]), bf16_lo(acc[j + 1]));
        }
    }
    #pragma unroll
    for (int j = 0; j < 24; ++j) {
        int oc = och * 24 + j;
        float other = __shfl_xor_sync(0xffffffffu, acc[j], 4);
        if (oc >= 32 && ((pos & 1) == 0)) {
            int vc = oc - 32;
            int o  = (b * 64 + vc) * 512 + (posg >> 1);
            g_v2h[o] = pack_bf16(acc[j], other);
            g_v2l[o] = pack_bf16(bf16_lo(acc[j]), bf16_lo(other));
        }
    }
}

// ---------------- flash attention (R11/R13 winner, unchanged) --------------
__global__ void __launch_bounds__(256) k_flash(
    const float* __restrict__ zw, const float* __restrict__ zb,
    float* __restrict__ out, int t)
{
    __shared__ uint32_t pool[12288];               // 48 KB

    const int b    = blockIdx.y;
    const int n0   = blockIdx.x * 128;
    const int tid  = threadIdx.x;
    const int w    = tid >> 5;
    const int lane = tid & 31;
    const int g    = lane >> 2, tt = lane & 3;
    const int rA   = w * 16 + g;

    float* q_s = reinterpret_cast<float*>(pool + 6144);   // [128][17]
    for (int i = tid; i < 2048; i += 256) {
        int c = i >> 7, r = i & 127;
        q_s[r * 17 + c] = g_q[(b * 16 + c) * 1024 + n0 + r];
    }
    __syncthreads();
    uint4 qh, ql;
    {
        float x0 = q_s[rA * 17 + 2 * tt],           x1 = q_s[rA * 17 + 2 * tt + 1];
        float x2 = q_s[(rA + 8) * 17 + 2 * tt],     x3 = q_s[(rA + 8) * 17 + 2 * tt + 1];
        float x4 = q_s[rA * 17 + 8 + 2 * tt],       x5 = q_s[rA * 17 + 9 + 2 * tt];
        float x6 = q_s[(rA + 8) * 17 + 8 + 2 * tt], x7 = q_s[(rA + 8) * 17 + 9 + 2 * tt];
        qh = make_uint4(pack_bf16(x0, x1), pack_bf16(x2, x3),
                        pack_bf16(x4, x5), pack_bf16(x6, x7));
        ql = make_uint4(pack_bf16(bf16_lo(x0), bf16_lo(x1)),
                        pack_bf16(bf16_lo(x2), bf16_lo(x3)),
                        pack_bf16(bf16_lo(x4), bf16_lo(x5)),
                        pack_bf16(bf16_lo(x6), bf16_lo(x7)));
    }

    uint32_t kh[2], kl[2], vh[8], vl[8];
    auto load_chunk = [&](int mc) {
        int kg = (b * 1024 + mc * 64) * 8;
        #pragma unroll
        for (int r = 0; r < 2; ++r) {
            kh[r] = g_k2h[kg + tid + r * 256];
            kl[r] = g_k2l[kg + tid + r * 256];
        }
        int vg = b * 64 * 512 + mc * 32;
        #pragma unroll
        for (int r = 0; r < 8; ++r) {
            int i = tid + r * 256;
            int c = i >> 5, mp = i & 31;
            vh[r] = g_v2h[vg + c * 512 + mp];
            vl[r] = g_v2l[vg + c * 512 + mp];
        }
    };
    auto store_chunk = [&](uint32_t* buf) {
        #pragma unroll
        for (int r = 0; r < 2; ++r) {
            int i = tid + r * 256;
            int m = i >> 3, c2 = i & 7;
            buf[m * 12 + c2]       = kh[r];
            buf[768 + m * 12 + c2] = kl[r];
        }
        #pragma unroll
        for (int r = 0; r < 8; ++r) {
            int i = tid + r * 256;
            int c = i >> 5, mp = i & 31;
            buf[1536 + c * 36 + mp] = vh[r];
            buf[3840 + c * 36 + mp] = vl[r];
        }
    };

    float z[8][4];
    #pragma unroll
    for (int cj = 0; cj < 8; ++cj)
        #pragma unroll
        for (int q = 0; q < 4; ++q) z[cj][q] = 0.f;
    float Ma = -1e30f, Mb = -1e30f, la = 0.f, lb = 0.f;

    load_chunk(0);
    store_chunk(pool);
    __syncthreads();

    for (int mch = 0; mch < 16; ++mch) {
        uint32_t* cur = pool + (mch & 1) * 6144;
        uint32_t* nxt = pool + ((mch + 1) & 1) * 6144;
        if (mch < 15) load_chunk(mch + 1);

        float S[8][4];
        #pragma unroll
        for (int j = 0; j < 8; ++j)
            #pragma unroll
            for (int q = 0; q < 4; ++q) S[j][q] = 0.f;
        #pragma unroll
        for (int j = 0; j < 8; ++j) {
            int m = j * 8 + g;
            uint2 bh = make_uint2(cur[m * 12 + tt],       cur[m * 12 + tt + 4]);
            uint2 bl = make_uint2(cur[768 + m * 12 + tt], cur[768 + m * 12 + tt + 4]);
            mma_bf16(S[j], qh, bh);
            mma_bf16(S[j], qh, bl);
            mma_bf16(S[j], ql, bh);
        }

        float cma = -1e30f, cmb = -1e30f;
        #pragma unroll
        for (int j = 0; j < 8; ++j) {
            cma = fmaxf(cma, fmaxf(S[j][0], S[j][1]));
            cmb = fmaxf(cmb, fmaxf(S[j][2], S[j][3]));
        }
        cma = fmaxf(cma, __shfl_xor_sync(0xffffffffu, cma, 1));
        cma = fmaxf(cma, __shfl_xor_sync(0xffffffffu, cma, 2));
        cmb = fmaxf(cmb, __shfl_xor_sync(0xffffffffu, cmb, 1));
        cmb = fmaxf(cmb, __shfl_xor_sync(0xffffffffu, cmb, 2));
        float Mna = fmaxf(Ma, cma), Mnb = fmaxf(Mb, cmb);
        float alA = __expf(Ma - Mna), alB = __expf(Mb - Mnb);
        Ma = Mna; Mb = Mnb;

        float sa = 0.f, sb = 0.f;
        #pragma unroll
        for (int j = 0; j < 8; ++j) {
            S[j][0] = __expf(S[j][0] - Ma); sa += S[j][0];
            S[j][1] = __expf(S[j][1] - Ma); sa += S[j][1];
            S[j][2] = __expf(S[j][2] - Mb); sb += S[j][2];
            S[j][3] = __expf(S[j][3] - Mb); sb += S[j][3];
        }
        sa += __shfl_xor_sync(0xffffffffu, sa, 1);
        sa += __shfl_xor_sync(0xffffffffu, sa, 2);
        sb += __shfl_xor_sync(0xffffffffu, sb, 1);
        sb += __shfl_xor_sync(0xffffffffu, sb, 2);
        la = la * alA + sa;
        lb = lb * alB + sb;
        #pragma unroll
        for (int cj = 0; cj < 8; ++cj) {
            z[cj][0] *= alA; z[cj][1] *= alA;
            z[cj][2] *= alB; z[cj][3] *= alB;
        }

        #pragma unroll
        for (int ks = 0; ks < 4; ++ks) {
            uint4 ah = make_uint4(
                pack_bf16(S[2 * ks][0], S[2 * ks][1]),
                pack_bf16(S[2 * ks][2], S[2 * ks][3]),
                pack_bf16(S[2 * ks + 1][0], S[2 * ks + 1][1]),
                pack_bf16(S[2 * ks + 1][2], S[2 * ks + 1][3]));
            uint4 al = make_uint4(
                pack_bf16(bf16_lo(S[2 * ks][0]), bf16_lo(S[2 * ks][1])),
                pack_bf16(bf16_lo(S[2 * ks][2]), bf16_lo(S[2 * ks][3])),
                pack_bf16(bf16_lo(S[2 * ks + 1][0]), bf16_lo(S[2 * ks + 1][1])),
                pack_bf16(bf16_lo(S[2 * ks + 1][2]), bf16_lo(S[2 * ks + 1][3])));
            #pragma unroll
            for (int cj = 0; cj < 8; ++cj) {
                int c = cj * 8 + g;
                uint2 bh = make_uint2(cur[1536 + c * 36 + ks * 8 + tt],
                                      cur[1536 + c * 36 + ks * 8 + tt + 4]);
                uint2 bl = make_uint2(cur[3840 + c * 36 + ks * 8 + tt],
                                      cur[3840 + c * 36 + ks * 8 + tt + 4]);
                mma_bf16(z[cj], ah, bh);
                mma_bf16(z[cj], ah, bl);
                mma_bf16(z[cj], al, bh);
            }
        }

        if (mch < 15) store_chunk(nxt);
        __syncthreads();
    }

    float* z_s  = reinterpret_cast<float*>(pool);          // [64][128]
    float* zw_s = reinterpret_cast<float*>(pool + 8192);   // 4096
    float lia = 1.f / la, lib = 1.f / lb;
    #pragma unroll
    for (int cj = 0; cj < 8; ++cj) {
        int c = cj * 8 + 2 * tt;
        z_s[ c      * 128 + w * 16 + g    ] = z[cj][0] * lia;
        z_s[(c + 1) * 128 + w * 16 + g    ] = z[cj][1] * lia;
        z_s[ c      * 128 + w * 16 + g + 8] = z[cj][2] * lib;
        z_s[(c + 1) * 128 + w * 16 + g + 8] = z[cj][3] * lib;
    }
    for (int i = tid; i < 4096; i += 256) zw_s[i] = zw[i];
    __syncthreads();

    const int l = lane;
    float acc2[8][4];
    #pragma unroll
    for (int ci = 0; ci < 8; ++ci) {
        float bv = zb[w * 8 + ci];
        #pragma unroll
        for (int i = 0; i < 4; ++i) acc2[ci][i] = bv;
    }
    #pragma unroll 8
    for (int c = 0; c < 64; ++c) {
        float pv[4];
        #pragma unroll
        for (int i = 0; i < 4; ++i) pv[i] = z_s[c * 128 + l + 32 * i];
        #pragma unroll
        for (int ci = 0; ci < 8; ++ci) {
            float wv = zw_s[(w * 8 + ci) * 64 + c];
            #pragma unroll
            for (int i = 0; i < 4; ++i) acc2[ci][i] += wv * pv[i];
        }
    }
    #pragma unroll
    for (int ci = 0; ci < 8; ++ci) {
        int oc = w * 8 + ci;
        #pragma unroll
        for (int i = 0; i < 4; ++i) {
            int n = n0 + l + 32 * i;
            float val = acc2[ci][i];
            g_h[(b * 64 + oc) * 1024 + n] = val;
            out[((b * 64 + oc) * 16 + t) * 1024 + n] = val;
        }
    }
}

// ---------------- orchestration --------------------------------------------
extern "C" void kernel_launch(void* const* d_in, const int* in_sizes, int n_in,
                              void* d_out, int out_size)
{
    (void)in_sizes; (void)n_in; (void)out_size;
    const float* X   = (const float*)d_in[0];
    const float* Wc  = (const float*)d_in[1];
    const float* bcc = (const float*)d_in[2];
    const float* Wci = (const float*)d_in[3];
    const float* Wcf = (const float*)d_in[4];
    const float* Wco = (const float*)d_in[5];
    const float* qw  = (const float*)d_in[6];
    const float* qb  = (const float*)d_in[7];
    const float* kw  = (const float*)d_in[8];
    const float* kb  = (const float*)d_in[9];
    const float* vw  = (const float*)d_in[10];
    const float* vb  = (const float*)d_in[11];
    const float* zw  = (const float*)d_in[12];
    const float* zb  = (const float*)d_in[13];
    float* out = (float*)d_out;

    cudaFuncSetAttribute(k_conv_mma,
                         cudaFuncAttributeMaxDynamicSharedMemorySize, 131072);

    k_init   <<<4096, 256>>>();
    k_prepw  <<<1152, 256>>>(Wc);
    k_preplut<<<9, 64>>>();
    for (int t = 0; t < NT; ++t) {
        k_conv_mma<<<dim3(8, 16, 2), 512, 131072>>>(X, t);
        k_gqkv    <<<dim3(8, 16),    512>>>(bcc, Wci, Wcf, Wco,
                                            qw, qb, kw, kb, vw, vb);
        k_flash   <<<dim3(8, 16),    256>>>(zw, zb, out, t);
    }
}

// round 16
// speedup vs baseline: 1.6596x; 1.1070x over previous
#include <cuda_runtime.h>
#include <cuda_bf16.h>
#include <math.h>
#include <cstdint>

#define BB 16
#define NT 16

// ---------------- persistent scratch (device globals; no allocation) -------
__device__ float g_c [16*64*1024];     // cell state
__device__ float g_q [16*16*1024];
__device__ float g_conv[16*256*1024];  // conv output (B,256,32,32), pre-bias
// packed bf16x2 hi/lo k and v (written by k_gqkv, read by k_flash)
__device__ uint32_t g_k2h[16*1024*8];  // [b][m][c2]
__device__ uint32_t g_k2l[16*1024*8];
__device__ uint32_t g_v2h[16*64*512];  // [b][c][mp]
__device__ uint32_t g_v2l[16*64*512];
// bf16 hi/lo split conv weights, fragment-linear, K = tap*128 + ci
__device__ uint32_t g_Wfrag[294912];
// pre-split conv A operands: X [b][t][pos][32 ch-pairs], h [b][pos][32 pairs]
__device__ uint32_t g_Xph[16*16*1024*32];   // 32 MB
__device__ uint32_t g_Xpl[16*16*1024*32];   // 32 MB
__device__ uint32_t g_Hph[16*1024*32];      // 2 MB (recurrent h, bf16 hi)
__device__ uint32_t g_Hpl[16*1024*32];      // 2 MB (bf16 lo)

// ---------------- helpers ---------------------------------------------------
__device__ __forceinline__ float sigf(float x) { return 1.f / (1.f + __expf(-x)); }
__device__ __forceinline__ float tanh_fast(float x)
{
    return __fdividef(2.f, 1.f + __expf(-2.f * x)) - 1.f;
}
__device__ __forceinline__ uint32_t pack_bf16(float a, float b)
{
    __nv_bfloat162 h2 = __floats2bfloat162_rn(a, b);
    return *reinterpret_cast<uint32_t*>(&h2);
}
__device__ __forceinline__ float bf16_lo(float a)
{
    return a - __bfloat162float(__float2bfloat16(a));
}
__device__ __forceinline__ void mma_bf16(float* c, uint4 a, uint2 b)
{
    asm volatile(
        "mma.sync.aligned.m16n8k16.row.col.f32.bf16.bf16.f32 "
        "{%0,%1,%2,%3}, {%4,%5,%6,%7}, {%8,%9}, {%0,%1,%2,%3};"
        : "+f"(c[0]), "+f"(c[1]), "+f"(c[2]), "+f"(c[3])
        : "r"(a.x), "r"(a.y), "r"(a.z), "r"(a.w), "r"(b.x), "r"(b.y));
}
__device__ __forceinline__ uint32_t smem_u32(const void* p)
{
    return (uint32_t)__cvta_generic_to_shared(p);
}
__device__ __forceinline__ void cpa4(uint32_t dst, const void* src, uint32_t sz)
{
    asm volatile("cp.async.ca.shared.global [%0], [%1], 4, %2;"
                 :: "r"(dst), "l"(src), "r"(sz));
}
__device__ __forceinline__ void cpa16(uint32_t dst, const void* src)
{
    asm volatile("cp.async.cg.shared.global [%0], [%1], 16;"
                 :: "r"(dst), "l"(src));
}
__device__ __forceinline__ void cpa_commit()
{
    asm volatile("cp.async.commit_group;" ::: "memory");
}
__device__ __forceinline__ void cpa_wait0()
{
    asm volatile("cp.async.wait_group 0;" ::: "memory");
}

// ---------------- init: zero c and h ----------------------------------------
__global__ void k_init()
{
    int i = blockIdx.x * 256 + threadIdx.x;   // 1,048,576
    g_c[i] = 0.f;
    if (i < 16 * 1024 * 32) { g_Hph[i] = 0u; g_Hpl[i] = 0u; }
}

// ---------------- X pre-split: [b][c][t][pos] fp32 -> [b][t][pos][cp] ------
__global__ void k_prepx(const float* __restrict__ X)
{
    int idx = blockIdx.x * 256 + threadIdx.x;   // 262144 = (b*16+t)*1024+pos
    int pos = idx & 1023;
    int bt  = idx >> 10;
    int b   = bt >> 4, t = bt & 15;
    const float* xb = X + (b * 64 * 16 + t) * 1024 + pos;
    #pragma unroll
    for (int c8 = 0; c8 < 8; ++c8) {
        float v[8];
        #pragma unroll
        for (int j = 0; j < 8; ++j) v[j] = xb[(c8 * 8 + j) * 16384];
        uint4 h4, l4;
        h4.x = pack_bf16(v[0], v[1]); l4.x = pack_bf16(bf16_lo(v[0]), bf16_lo(v[1]));
        h4.y = pack_bf16(v[2], v[3]); l4.y = pack_bf16(bf16_lo(v[2]), bf16_lo(v[3]));
        h4.z = pack_bf16(v[4], v[5]); l4.z = pack_bf16(bf16_lo(v[4]), bf16_lo(v[5]));
        h4.w = pack_bf16(v[6], v[7]); l4.w = pack_bf16(bf16_lo(v[6]), bf16_lo(v[7]));
        *reinterpret_cast<uint4*>(g_Xph + idx * 32 + c8 * 4) = h4;
        *reinterpret_cast<uint4*>(g_Xpl + idx * 32 + c8 * 4) = l4;
    }
}

// ---------------- weight prep: K = tap*128 + ci ordering --------------------
__global__ void k_prepw(const float* __restrict__ Wc)
{
    int idx   = blockIdx.x * 256 + threadIdx.x;   // 294912
    int inner = idx & 4095;
    int outer = idx >> 12;
    int c0    = outer % 18;
    int gate  = outer / 18;
    int s     = inner & 1;
    int lane  = (inner >> 1) & 31;
    int ki    = (inner >> 6) & 3;
    int ni    = (inner >> 8) & 7;
    int sp    = (inner >> 11) & 1;

    int g = lane >> 2, tt = lane & 3;
    int n_global = gate * 64 + ni * 8 + g;
    int k0 = c0 * 64 + ki * 16 + 2 * tt + 8 * s;   // K order: tap*128 + ci
    int tap = k0 >> 7, ci = k0 & 127;

    float w0 = Wc[(n_global * 128 + ci) * 9 + tap];
    float w1 = Wc[(n_global * 128 + ci + 1) * 9 + tap];
    if (sp == 1) { w0 = bf16_lo(w0); w1 = bf16_lo(w1); }
    g_Wfrag[idx] = pack_bf16(w0, w1);
}

// ---------------- conv via mma.sync bf16: cp.async pipelined staging --------
// grid (8 m-tiles, 16 batch, 2 gate-pairs), 512 threads = 16 warps (4m x 4n).
// Dynamic smem 128 KB: 2 x [Ah 4096u | Al 4096u | Bh 4096u | Bl 4096u].
// K is tap-major: chunk c0 -> tap=c0>>1 (uniform shift), half=c0&1 (X vs h).
__global__ void __launch_bounds__(512, 1) k_conv_mma(int t)
{
    extern __shared__ uint32_t sm_u[];     // 32768 u32 = 128 KB

    const int tid  = threadIdx.x;
    const int wid  = tid >> 5;
    const int lane = tid & 31;
    const int mt   = blockIdx.x;
    const int b    = blockIdx.y;
    const int gp   = blockIdx.z;
    const int wm   = wid >> 2;
    const int wn   = wid & 3;
    const int g    = lane >> 2, tt = lane & 3;

    const uint32_t sbase = smem_u32(sm_u);

    float acc[2][4][4];
    #pragma unroll
    for (int im = 0; im < 2; ++im)
        #pragma unroll
        for (int in = 0; in < 4; ++in)
            #pragma unroll
            for (int q = 0; q < 4; ++q) acc[im][in][q] = 0.f;

    auto stage = [&](int bufsel, int c0) {
        const uint32_t abase = sbase + bufsel * 65536;
        const int tap  = c0 >> 1;
        const int half = c0 & 1;
        const int dy = tap / 3 - 1;
        const int dx = tap - (tap / 3) * 3 - 1;
        const uint32_t* sH = half ? (g_Hph + b * 32768)
                                  : (g_Xph + (b * 16 + t) * 32768);
        const uint32_t* sL = half ? (g_Hpl + b * 32768)
                                  : (g_Xpl + (b * 16 + t) * 32768);
        // A: 8 slots/thread, hi+lo
        #pragma unroll
        for (int j = 0; j < 8; ++j) {
            int slot = j * 512 + tid;
            int s  = slot & 3;
            int ln = (slot >> 2) & 31;
            int ki = (slot >> 7) & 3;
            int mi = slot >> 9;
            int gg = ln >> 2, t4 = ln & 3;
            int m    = mi * 16 + gg + 8 * (s & 1);
            int cp_l = ki * 8 + t4 + 4 * (s >> 1);
            int pix = mt * 128 + m;
            int sy = (pix >> 5) + dy, sx = (pix & 31) + dx;
            bool valid = ((unsigned)sy < 32u) && ((unsigned)sx < 32u);
            int off = (valid ? sy * 32 + sx : 0) * 32 + cp_l;
            uint32_t sz = valid ? 4u : 0u;
            cpa4(abase + slot * 4,         sH + off, sz);
            cpa4(abase + 16384 + slot * 4, sL + off, sz);
        }
        // B: 2 gates, hi+lo: 4 x cp.async.16B
        #pragma unroll
        for (int gsel = 0; gsel < 2; ++gsel) {
            const uint32_t* wsrc = g_Wfrag + ((2 * gp + gsel) * 18 + c0) * 4096;
            uint32_t bdst = abase + 32768 + (gsel * 2048 + tid * 4) * 4;
            cpa16(bdst,         wsrc + tid * 4);
            cpa16(bdst + 16384, wsrc + 2048 + tid * 4);
        }
    };

    // prologue
    stage(0, 0);
    cpa_commit();
    cpa_wait0();
    __syncthreads();

    for (int c0 = 0; c0 < 18; ++c0) {
        uint32_t* cur = sm_u + (c0 & 1) * 16384;
        if (c0 < 17) { stage((c0 + 1) & 1, c0 + 1); cpa_commit(); }

        const uint4* Ah4 = reinterpret_cast<const uint4*>(cur);
        const uint4* Al4 = reinterpret_cast<const uint4*>(cur + 4096);
        const uint2* Bh2 = reinterpret_cast<const uint2*>(cur + 8192);
        const uint2* Bl2 = reinterpret_cast<const uint2*>(cur + 12288);

        #pragma unroll
        for (int ki = 0; ki < 4; ++ki) {
            uint4 a0h = Ah4[((wm * 2    ) * 4 + ki) * 32 + lane];
            uint4 a1h = Ah4[((wm * 2 + 1) * 4 + ki) * 32 + lane];
            uint4 a0l = Al4[((wm * 2    ) * 4 + ki) * 32 + lane];
            uint4 a1l = Al4[((wm * 2 + 1) * 4 + ki) * 32 + lane];
            #pragma unroll
            for (int in = 0; in < 4; ++in) {
                int ni   = wn * 4 + in;
                int bidx = (ni >> 3) * 1024 + ((ni & 7) * 4 + ki) * 32 + lane;
                uint2 bh = Bh2[bidx];
                uint2 bl = Bl2[bidx];
                mma_bf16(acc[0][in], a0h, bh);
                mma_bf16(acc[1][in], a1h, bh);
                mma_bf16(acc[0][in], a0h, bl);
                mma_bf16(acc[1][in], a1h, bl);
                mma_bf16(acc[0][in], a0l, bh);
                mma_bf16(acc[1][in], a1l, bh);
            }
        }
        cpa_wait0();
        __syncthreads();
    }

    // ---- epilogue: two 64-n passes through smem, coalesced writes ----
    float* out_s = reinterpret_cast<float*>(sm_u);   // 64 x 132 floats
    #pragma unroll
    for (int p = 0; p < 2; ++p) {
        __syncthreads();
        #pragma unroll
        for (int im = 0; im < 2; ++im) {
            int m = (wm * 2 + im) * 16 + g;
            #pragma unroll
            for (int in = 0; in < 4; ++in) {
                int ni = wn * 4 + in;
                if ((ni >> 3) == p) {
                    int n = (ni & 7) * 8 + 2 * tt;
                    out_s[ n      * 132 + m    ] = acc[im][in][0];
                    out_s[(n + 1) * 132 + m    ] = acc[im][in][1];
                    out_s[ n      * 132 + m + 8] = acc[im][in][2];
                    out_s[(n + 1) * 132 + m + 8] = acc[im][in][3];
                }
            }
        }
        __syncthreads();
        #pragma unroll
        for (int j = 0; j < 16; ++j) {
            int idx = j * 512 + tid;                 // 8192 = 64n x 128m
            int n = idx >> 7, m = idx & 127;
            g_conv[(b * 256 + (2 * gp + p) * 64 + n) * 1024 + mt * 128 + m]
                = out_s[n * 132 + m];
        }
    }
}

// ---------------- fused gate + qkv (R13 winner, unchanged) -----------------
__global__ void __launch_bounds__(512) k_gqkv(
    const float* __restrict__ bc,
    const float* __restrict__ Wci, const float* __restrict__ Wcf,
    const float* __restrict__ Wco,
    const float* __restrict__ qw,  const float* __restrict__ qb,
    const float* __restrict__ kw,  const float* __restrict__ kb,
    const float* __restrict__ vw,  const float* __restrict__ vb)
{
    __shared__ float h_s[32 * 128];    // 16 KB
    __shared__ float w_s[96 * 33];     // 12.7 KB

    const int pt   = blockIdx.x;
    const int b    = blockIdx.y;
    const int tid  = threadIdx.x;
    const int pos  = tid >> 2;
    const int och  = tid & 3;
    const int posg = pt * 128 + pos;

    float acc[24];
    #pragma unroll
    for (int j = 0; j < 24; ++j) {
        int oc = och * 24 + j;
        acc[j] = (oc < 16) ? qb[oc] : (oc < 32) ? kb[oc - 16] : vb[oc - 32];
    }

    for (int ch = 0; ch < 2; ++ch) {
        for (int i = tid; i < 3072; i += 512) {
            int oc = i >> 5, c = i & 31;
            int cg = ch * 32 + c;
            float wv = (oc < 16) ? qw[oc * 64 + cg]
                     : (oc < 32) ? kw[(oc - 16) * 64 + cg]
                                 : vw[(oc - 32) * 64 + cg];
            w_s[oc * 33 + c] = wv;
        }
        #pragma unroll
        for (int r = 0; r < 8; ++r) {
            int i = tid + r * 512;
            int c = i >> 7, p = i & 127;
            int cg = ch * 32 + c;
            int pg = pt * 128 + p;
            int idx = (b * 64 + cg) * 1024 + pg;
            int cb  = (b * 256 + cg) * 1024 + pg;
            float ic = g_conv[cb]              + bc[cg];
            float fc = g_conv[cb + 64 * 1024]  + bc[64 + cg];
            float gc = g_conv[cb + 128 * 1024] + bc[128 + cg];
            float oc = g_conv[cb + 192 * 1024] + bc[192 + cg];
            float cp = g_c[idx];
            int   wp = cg * 1024 + pg;
            float ii = sigf(ic + Wci[wp] * cp);
            float ff = sigf(fc + Wcf[wp] * cp);
            float nc = ff * cp + ii * tanh_fast(gc);
            float oo = sigf(oc + Wco[wp] * nc);
            g_c[idx] = nc;
            h_s[c * 128 + p] = oo * tanh_fast(nc);
        }
        __syncthreads();
        #pragma unroll 8
        for (int c = 0; c < 32; ++c) {
            float hv = h_s[c * 128 + pos];
            #pragma unroll
            for (int j = 0; j < 24; ++j)
                acc[j] += w_s[(och * 24 + j) * 33 + c] * hv;
        }
        __syncthreads();
    }

    if (och == 0) {
        #pragma unroll
        for (int j = 0; j < 16; ++j)
            g_q[(b * 16 + j) * 1024 + posg] = acc[j];
    }
    #pragma unroll
    for (int j = 0; j < 24; j += 2) {
        int oc = och * 24 + j;
        if (oc >= 16 && oc < 32) {
            int c2 = (oc - 16) >> 1;
            int o  = (b * 1024 + posg) * 8 + c2;
            g_k2h[o] = pack_bf16(acc[j], acc[j + 1]);
            g_k2l[o] = pack_bf16(bf16_lo(acc[j]), bf16_lo(acc[j + 1]));
        }
    }
    #pragma unroll
    for (int j = 0; j < 24; ++j) {
        int oc = och * 24 + j;
        float other = __shfl_xor_sync(0xffffffffu, acc[j], 4);
        if (oc >= 32 && ((pos & 1) == 0)) {
            int vc = oc - 32;
            int o  = (b * 64 + vc) * 512 + (posg >> 1);
            g_v2h[o] = pack_bf16(acc[j], other);
            g_v2l[o] = pack_bf16(bf16_lo(acc[j]), bf16_lo(other));
        }
    }
}

// ---------------- flash attention (R11/R13 winner; writes packed h) --------
__global__ void __launch_bounds__(256) k_flash(
    const float* __restrict__ zw, const float* __restrict__ zb,
    float* __restrict__ out, int t)
{
    __shared__ uint32_t pool[12288];               // 48 KB

    const int b    = blockIdx.y;
    const int n0   = blockIdx.x * 128;
    const int tid  = threadIdx.x;
    const int w    = tid >> 5;
    const int lane = tid & 31;
    const int g    = lane >> 2, tt = lane & 3;
    const int rA   = w * 16 + g;

    float* q_s = reinterpret_cast<float*>(pool + 6144);   // [128][17]
    for (int i = tid; i < 2048; i += 256) {
        int c = i >> 7, r = i & 127;
        q_s[r * 17 + c] = g_q[(b * 16 + c) * 1024 + n0 + r];
    }
    __syncthreads();
    uint4 qh, ql;
    {
        float x0 = q_s[rA * 17 + 2 * tt],           x1 = q_s[rA * 17 + 2 * tt + 1];
        float x2 = q_s[(rA + 8) * 17 + 2 * tt],     x3 = q_s[(rA + 8) * 17 + 2 * tt + 1];
        float x4 = q_s[rA * 17 + 8 + 2 * tt],       x5 = q_s[rA * 17 + 9 + 2 * tt];
        float x6 = q_s[(rA + 8) * 17 + 8 + 2 * tt], x7 = q_s[(rA + 8) * 17 + 9 + 2 * tt];
        qh = make_uint4(pack_bf16(x0, x1), pack_bf16(x2, x3),
                        pack_bf16(x4, x5), pack_bf16(x6, x7));
        ql = make_uint4(pack_bf16(bf16_lo(x0), bf16_lo(x1)),
                        pack_bf16(bf16_lo(x2), bf16_lo(x3)),
                        pack_bf16(bf16_lo(x4), bf16_lo(x5)),
                        pack_bf16(bf16_lo(x6), bf16_lo(x7)));
    }

    uint32_t kh[2], kl[2], vh[8], vl[8];
    auto load_chunk = [&](int mc) {
        int kg = (b * 1024 + mc * 64) * 8;
        #pragma unroll
        for (int r = 0; r < 2; ++r) {
            kh[r] = g_k2h[kg + tid + r * 256];
            kl[r] = g_k2l[kg + tid + r * 256];
        }
        int vg = b * 64 * 512 + mc * 32;
        #pragma unroll
        for (int r = 0; r < 8; ++r) {
            int i = tid + r * 256;
            int c = i >> 5, mp = i & 31;
            vh[r] = g_v2h[vg + c * 512 + mp];
            vl[r] = g_v2l[vg + c * 512 + mp];
        }
    };
    auto store_chunk = [&](uint32_t* buf) {
        #pragma unroll
        for (int r = 0; r < 2; ++r) {
            int i = tid + r * 256;
            int m = i >> 3, c2 = i & 7;
            buf[m * 12 + c2]       = kh[r];
            buf[768 + m * 12 + c2] = kl[r];
        }
        #pragma unroll
        for (int r = 0; r < 8; ++r) {
            int i = tid + r * 256;
            int c = i >> 5, mp = i & 31;
            buf[1536 + c * 36 + mp] = vh[r];
            buf[3840 + c * 36 + mp] = vl[r];
        }
    };

    float z[8][4];
    #pragma unroll
    for (int cj = 0; cj < 8; ++cj)
        #pragma unroll
        for (int q = 0; q < 4; ++q) z[cj][q] = 0.f;
    float Ma = -1e30f, Mb = -1e30f, la = 0.f, lb = 0.f;

    load_chunk(0);
    store_chunk(pool);
    __syncthreads();

    for (int mch = 0; mch < 16; ++mch) {
        uint32_t* cur = pool + (mch & 1) * 6144;
        uint32_t* nxt = pool + ((mch + 1) & 1) * 6144;
        if (mch < 15) load_chunk(mch + 1);

        float S[8][4];
        #pragma unroll
        for (int j = 0; j < 8; ++j)
            #pragma unroll
            for (int q = 0; q < 4; ++q) S[j][q] = 0.f;
        #pragma unroll
        for (int j = 0; j < 8; ++j) {
            int m = j * 8 + g;
            uint2 bh = make_uint2(cur[m * 12 + tt],       cur[m * 12 + tt + 4]);
            uint2 bl = make_uint2(cur[768 + m * 12 + tt], cur[768 + m * 12 + tt + 4]);
            mma_bf16(S[j], qh, bh);
            mma_bf16(S[j], qh, bl);
            mma_bf16(S[j], ql, bh);
        }

        float cma = -1e30f, cmb = -1e30f;
        #pragma unroll
        for (int j = 0; j < 8; ++j) {
            cma = fmaxf(cma, fmaxf(S[j][0], S[j][1]));
            cmb = fmaxf(cmb, fmaxf(S[j][2], S[j][3]));
        }
        cma = fmaxf(cma, __shfl_xor_sync(0xffffffffu, cma, 1));
        cma = fmaxf(cma, __shfl_xor_sync(0xffffffffu, cma, 2));
        cmb = fmaxf(cmb, __shfl_xor_sync(0xffffffffu, cmb, 1));
        cmb = fmaxf(cmb, __shfl_xor_sync(0xffffffffu, cmb, 2));
        float Mna = fmaxf(Ma, cma), Mnb = fmaxf(Mb, cmb);
        float alA = __expf(Ma - Mna), alB = __expf(Mb - Mnb);
        Ma = Mna; Mb = Mnb;

        float sa = 0.f, sb = 0.f;
        #pragma unroll
        for (int j = 0; j < 8; ++j) {
            S[j][0] = __expf(S[j][0] - Ma); sa += S[j][0];
            S[j][1] = __expf(S[j][1] - Ma); sa += S[j][1];
            S[j][2] = __expf(S[j][2] - Mb); sb += S[j][2];
            S[j][3] = __expf(S[j][3] - Mb); sb += S[j][3];
        }
        sa += __shfl_xor_sync(0xffffffffu, sa, 1);
        sa += __shfl_xor_sync(0xffffffffu, sa, 2);
        sb += __shfl_xor_sync(0xffffffffu, sb, 1);
        sb += __shfl_xor_sync(0xffffffffu, sb, 2);
        la = la * alA + sa;
        lb = lb * alB + sb;
        #pragma unroll
        for (int cj = 0; cj < 8; ++cj) {
            z[cj][0] *= alA; z[cj][1] *= alA;
            z[cj][2] *= alB; z[cj][3] *= alB;
        }

        #pragma unroll
        for (int ks = 0; ks < 4; ++ks) {
            uint4 ah = make_uint4(
                pack_bf16(S[2 * ks][0], S[2 * ks][1]),
                pack_bf16(S[2 * ks][2], S[2 * ks][3]),
                pack_bf16(S[2 * ks + 1][0], S[2 * ks + 1][1]),
                pack_bf16(S[2 * ks + 1][2], S[2 * ks + 1][3]));
            uint4 al = make_uint4(
                pack_bf16(bf16_lo(S[2 * ks][0]), bf16_lo(S[2 * ks][1])),
                pack_bf16(bf16_lo(S[2 * ks][2]), bf16_lo(S[2 * ks][3])),
                pack_bf16(bf16_lo(S[2 * ks + 1][0]), bf16_lo(S[2 * ks + 1][1])),
                pack_bf16(bf16_lo(S[2 * ks + 1][2]), bf16_lo(S[2 * ks + 1][3])));
            #pragma unroll
            for (int cj = 0; cj < 8; ++cj) {
                int c = cj * 8 + g;
                uint2 bh = make_uint2(cur[1536 + c * 36 + ks * 8 + tt],
                                      cur[1536 + c * 36 + ks * 8 + tt + 4]);
                uint2 bl = make_uint2(cur[3840 + c * 36 + ks * 8 + tt],
                                      cur[3840 + c * 36 + ks * 8 + tt + 4]);
                mma_bf16(z[cj], ah, bh);
                mma_bf16(z[cj], ah, bl);
                mma_bf16(z[cj], al, bh);
            }
        }

        if (mch < 15) store_chunk(nxt);
        __syncthreads();
    }

    float* z_s  = reinterpret_cast<float*>(pool);          // [64][128]
    float* zw_s = reinterpret_cast<float*>(pool + 8192);   // 4096
    float lia = 1.f / la, lib = 1.f / lb;
    #pragma unroll
    for (int cj = 0; cj < 8; ++cj) {
        int c = cj * 8 + 2 * tt;
        z_s[ c      * 128 + w * 16 + g    ] = z[cj][0] * lia;
        z_s[(c + 1) * 128 + w * 16 + g    ] = z[cj][1] * lia;
        z_s[ c      * 128 + w * 16 + g + 8] = z[cj][2] * lib;
        z_s[(c + 1) * 128 + w * 16 + g + 8] = z[cj][3] * lib;
    }
    for (int i = tid; i < 4096; i += 256) zw_s[i] = zw[i];
    __syncthreads();

    const int l = lane;
    float acc2[8][4];
    #pragma unroll
    for (int ci = 0; ci < 8; ++ci) {
        float bv = zb[w * 8 + ci];
        #pragma unroll
        for (int i = 0; i < 4; ++i) acc2[ci][i] = bv;
    }
    #pragma unroll 8
    for (int c = 0; c < 64; ++c) {
        float pv[4];
        #pragma unroll
        for (int i = 0; i < 4; ++i) pv[i] = z_s[c * 128 + l + 32 * i];
        #pragma unroll
        for (int ci = 0; ci < 8; ++ci) {
            float wv = zw_s[(w * 8 + ci) * 64 + c];
            #pragma unroll
            for (int i = 0; i < 4; ++i) acc2[ci][i] += wv * pv[i];
        }
    }
    // write output + packed bf16 hi/lo recurrent h (channel pairs in-thread)
    #pragma unroll
    for (int ci = 0; ci < 8; ++ci) {
        int oc = w * 8 + ci;
        #pragma unroll
        for (int i = 0; i < 4; ++i) {
            int n = n0 + l + 32 * i;
            out[((b * 64 + oc) * 16 + t) * 1024 + n] = acc2[ci][i];
        }
    }
    #pragma unroll
    for (int e = 0; e < 4; ++e) {
        #pragma unroll
        for (int i = 0; i < 4; ++i) {
            int n = n0 + l + 32 * i;
            int o = (b * 1024 + n) * 32 + w * 4 + e;
            g_Hph[o] = pack_bf16(acc2[2 * e][i], acc2[2 * e + 1][i]);
            g_Hpl[o] = pack_bf16(bf16_lo(acc2[2 * e][i]),
                                 bf16_lo(acc2[2 * e + 1][i]));
        }
    }
}

// ---------------- orchestration --------------------------------------------
extern "C" void kernel_launch(void* const* d_in, const int* in_sizes, int n_in,
                              void* d_out, int out_size)
{
    (void)in_sizes; (void)n_in; (void)out_size;
    const float* X   = (const float*)d_in[0];
    const float* Wc  = (const float*)d_in[1];
    const float* bcc = (const float*)d_in[2];
    const float* Wci = (const float*)d_in[3];
    const float* Wcf = (const float*)d_in[4];
    const float* Wco = (const float*)d_in[5];
    const float* qw  = (const float*)d_in[6];
    const float* qb  = (const float*)d_in[7];
    const float* kw  = (const float*)d_in[8];
    const float* kb  = (const float*)d_in[9];
    const float* vw  = (const float*)d_in[10];
    const float* vb  = (const float*)d_in[11];
    const float* zw  = (const float*)d_in[12];
    const float* zb  = (const float*)d_in[13];
    float* out = (float*)d_out;

    cudaFuncSetAttribute(k_conv_mma,
                         cudaFuncAttributeMaxDynamicSharedMemorySize, 131072);

    k_init <<<4096, 256>>>();
    k_prepx<<<1024, 256>>>(X);
    k_prepw<<<1152, 256>>>(Wc);
    for (int t = 0; t < NT; ++t) {
        k_conv_mma<<<dim3(8, 16, 2), 512, 131072>>>(t);
        k_gqkv    <<<dim3(8, 16),    512>>>(bcc, Wci, Wcf, Wco,
                                            qw, qb, kw, kb, vw, vb);
        k_flash   <<<dim3(8, 16),    256>>>(zw, zb, out, t);
    }
}

// round 17
// speedup vs baseline: 1.6851x; 1.0154x over previous
#include <cuda_runtime.h>
#include <cuda_bf16.h>
#include <math.h>
#include <cstdint>

#define BB 16
#define NT 16

// ---------------- persistent scratch (device globals; no allocation) -------
__device__ float g_c [16*64*1024];     // cell state
__device__ float g_q [16*16*1024];
__device__ float g_conv[16*256*1024];  // conv output (B,256,32,32), pre-bias
// packed bf16x2 hi/lo k and v (written by k_gqkv, read by k_flash)
__device__ uint32_t g_k2h[16*1024*8];  // [b][m][c2]
__device__ uint32_t g_k2l[16*1024*8];
__device__ uint32_t g_v2h[16*64*512];  // [b][c][mp]
__device__ uint32_t g_v2l[16*64*512];
// bf16 hi/lo split conv weights, fragment-linear, K = tap*128 + ci
__device__ uint32_t g_Wfrag[294912];
// pre-split conv A operands: X [b][t][pos][32 ch-pairs], h [b][pos][32 pairs]
__device__ uint32_t g_Xph[16*16*1024*32];   // 32 MB
__device__ uint32_t g_Xpl[16*16*1024*32];   // 32 MB
__device__ uint32_t g_Hph[16*1024*32];      // 2 MB
__device__ uint32_t g_Hpl[16*1024*32];      // 2 MB

// ---------------- helpers ---------------------------------------------------
__device__ __forceinline__ float sigf(float x) { return 1.f / (1.f + __expf(-x)); }
__device__ __forceinline__ float tanh_fast(float x)
{
    return __fdividef(2.f, 1.f + __expf(-2.f * x)) - 1.f;
}
__device__ __forceinline__ uint32_t pack_bf16(float a, float b)
{
    __nv_bfloat162 h2 = __floats2bfloat162_rn(a, b);
    return *reinterpret_cast<uint32_t*>(&h2);
}
__device__ __forceinline__ float bf16_lo(float a)
{
    return a - __bfloat162float(__float2bfloat16(a));
}
__device__ __forceinline__ void mma_bf16(float* c, uint4 a, uint2 b)
{
    asm volatile(
        "mma.sync.aligned.m16n8k16.row.col.f32.bf16.bf16.f32 "
        "{%0,%1,%2,%3}, {%4,%5,%6,%7}, {%8,%9}, {%0,%1,%2,%3};"
        : "+f"(c[0]), "+f"(c[1]), "+f"(c[2]), "+f"(c[3])
        : "r"(a.x), "r"(a.y), "r"(a.z), "r"(a.w), "r"(b.x), "r"(b.y));
}
__device__ __forceinline__ uint32_t smem_u32(const void* p)
{
    return (uint32_t)__cvta_generic_to_shared(p);
}
__device__ __forceinline__ void cpa4(uint32_t dst, const void* src, uint32_t sz)
{
    asm volatile("cp.async.ca.shared.global [%0], [%1], 4, %2;"
                 :: "r"(dst), "l"(src), "r"(sz));
}
__device__ __forceinline__ void cpa16(uint32_t dst, const void* src)
{
    asm volatile("cp.async.cg.shared.global [%0], [%1], 16;"
                 :: "r"(dst), "l"(src));
}
__device__ __forceinline__ void cpa_commit()
{
    asm volatile("cp.async.commit_group;" ::: "memory");
}
__device__ __forceinline__ void cpa_wait0()
{
    asm volatile("cp.async.wait_group 0;" ::: "memory");
}

// ---------------- init: zero c and h ----------------------------------------
__global__ void k_init()
{
    int i = blockIdx.x * 256 + threadIdx.x;   // 1,048,576
    g_c[i] = 0.f;
    if (i < 16 * 1024 * 32) { g_Hph[i] = 0u; g_Hpl[i] = 0u; }
}

// ---------------- X pre-split ------------------------------------------------
__global__ void k_prepx(const float* __restrict__ X)
{
    int idx = blockIdx.x * 256 + threadIdx.x;   // 262144
    int pos = idx & 1023;
    int bt  = idx >> 10;
    int b   = bt >> 4, t = bt & 15;
    const float* xb = X + (b * 64 * 16 + t) * 1024 + pos;
    #pragma unroll
    for (int c8 = 0; c8 < 8; ++c8) {
        float v[8];
        #pragma unroll
        for (int j = 0; j < 8; ++j) v[j] = xb[(c8 * 8 + j) * 16384];
        uint4 h4, l4;
        h4.x = pack_bf16(v[0], v[1]); l4.x = pack_bf16(bf16_lo(v[0]), bf16_lo(v[1]));
        h4.y = pack_bf16(v[2], v[3]); l4.y = pack_bf16(bf16_lo(v[2]), bf16_lo(v[3]));
        h4.z = pack_bf16(v[4], v[5]); l4.z = pack_bf16(bf16_lo(v[4]), bf16_lo(v[5]));
        h4.w = pack_bf16(v[6], v[7]); l4.w = pack_bf16(bf16_lo(v[6]), bf16_lo(v[7]));
        *reinterpret_cast<uint4*>(g_Xph + idx * 32 + c8 * 4) = h4;
        *reinterpret_cast<uint4*>(g_Xpl + idx * 32 + c8 * 4) = l4;
    }
}

// ---------------- weight prep: K = tap*128 + ci ordering --------------------
__global__ void k_prepw(const float* __restrict__ Wc)
{
    int idx   = blockIdx.x * 256 + threadIdx.x;   // 294912
    int inner = idx & 4095;
    int outer = idx >> 12;
    int c0    = outer % 18;
    int gate  = outer / 18;
    int s     = inner & 1;
    int lane  = (inner >> 1) & 31;
    int ki    = (inner >> 6) & 3;
    int ni    = (inner >> 8) & 7;
    int sp    = (inner >> 11) & 1;

    int g = lane >> 2, tt = lane & 3;
    int n_global = gate * 64 + ni * 8 + g;
    int k0 = c0 * 64 + ki * 16 + 2 * tt + 8 * s;
    int tap = k0 >> 7, ci = k0 & 127;

    float w0 = Wc[(n_global * 128 + ci) * 9 + tap];
    float w1 = Wc[(n_global * 128 + ci + 1) * 9 + tap];
    if (sp == 1) { w0 = bf16_lo(w0); w1 = bf16_lo(w1); }
    g_Wfrag[idx] = pack_bf16(w0, w1);
}

// ---------------- conv via mma.sync bf16 (R16 winner, unchanged) ------------
__global__ void __launch_bounds__(512, 1) k_conv_mma(int t)
{
    extern __shared__ uint32_t sm_u[];     // 32768 u32 = 128 KB

    const int tid  = threadIdx.x;
    const int wid  = tid >> 5;
    const int lane = tid & 31;
    const int mt   = blockIdx.x;
    const int b    = blockIdx.y;
    const int gp   = blockIdx.z;
    const int wm   = wid >> 2;
    const int wn   = wid & 3;
    const int g    = lane >> 2, tt = lane & 3;

    const uint32_t sbase = smem_u32(sm_u);

    float acc[2][4][4];
    #pragma unroll
    for (int im = 0; im < 2; ++im)
        #pragma unroll
        for (int in = 0; in < 4; ++in)
            #pragma unroll
            for (int q = 0; q < 4; ++q) acc[im][in][q] = 0.f;

    auto stage = [&](int bufsel, int c0) {
        const uint32_t abase = sbase + bufsel * 65536;
        const int tap  = c0 >> 1;
        const int half = c0 & 1;
        const int dy = tap / 3 - 1;
        const int dx = tap - (tap / 3) * 3 - 1;
        const uint32_t* sH = half ? (g_Hph + b * 32768)
                                  : (g_Xph + (b * 16 + t) * 32768);
        const uint32_t* sL = half ? (g_Hpl + b * 32768)
                                  : (g_Xpl + (b * 16 + t) * 32768);
        #pragma unroll
        for (int j = 0; j < 8; ++j) {
            int slot = j * 512 + tid;
            int s  = slot & 3;
            int ln = (slot >> 2) & 31;
            int ki = (slot >> 7) & 3;
            int mi = slot >> 9;
            int gg = ln >> 2, t4 = ln & 3;
            int m    = mi * 16 + gg + 8 * (s & 1);
            int cp_l = ki * 8 + t4 + 4 * (s >> 1);
            int pix = mt * 128 + m;
            int sy = (pix >> 5) + dy, sx = (pix & 31) + dx;
            bool valid = ((unsigned)sy < 32u) && ((unsigned)sx < 32u);
            int off = (valid ? sy * 32 + sx : 0) * 32 + cp_l;
            uint32_t sz = valid ? 4u : 0u;
            cpa4(abase + slot * 4,         sH + off, sz);
            cpa4(abase + 16384 + slot * 4, sL + off, sz);
        }
        #pragma unroll
        for (int gsel = 0; gsel < 2; ++gsel) {
            const uint32_t* wsrc = g_Wfrag + ((2 * gp + gsel) * 18 + c0) * 4096;
            uint32_t bdst = abase + 32768 + (gsel * 2048 + tid * 4) * 4;
            cpa16(bdst,         wsrc + tid * 4);
            cpa16(bdst + 16384, wsrc + 2048 + tid * 4);
        }
    };

    stage(0, 0);
    cpa_commit();
    cpa_wait0();
    __syncthreads();

    for (int c0 = 0; c0 < 18; ++c0) {
        uint32_t* cur = sm_u + (c0 & 1) * 16384;
        if (c0 < 17) { stage((c0 + 1) & 1, c0 + 1); cpa_commit(); }

        const uint4* Ah4 = reinterpret_cast<const uint4*>(cur);
        const uint4* Al4 = reinterpret_cast<const uint4*>(cur + 4096);
        const uint2* Bh2 = reinterpret_cast<const uint2*>(cur + 8192);
        const uint2* Bl2 = reinterpret_cast<const uint2*>(cur + 12288);

        #pragma unroll
        for (int ki = 0; ki < 4; ++ki) {
            uint4 a0h = Ah4[((wm * 2    ) * 4 + ki) * 32 + lane];
            uint4 a1h = Ah4[((wm * 2 + 1) * 4 + ki) * 32 + lane];
            uint4 a0l = Al4[((wm * 2    ) * 4 + ki) * 32 + lane];
            uint4 a1l = Al4[((wm * 2 + 1) * 4 + ki) * 32 + lane];
            #pragma unroll
            for (int in = 0; in < 4; ++in) {
                int ni   = wn * 4 + in;
                int bidx = (ni >> 3) * 1024 + ((ni & 7) * 4 + ki) * 32 + lane;
                uint2 bh = Bh2[bidx];
                uint2 bl = Bl2[bidx];
                mma_bf16(acc[0][in], a0h, bh);
                mma_bf16(acc[1][in], a1h, bh);
                mma_bf16(acc[0][in], a0h, bl);
                mma_bf16(acc[1][in], a1h, bl);
                mma_bf16(acc[0][in], a0l, bh);
                mma_bf16(acc[1][in], a1l, bh);
            }
        }
        cpa_wait0();
        __syncthreads();
    }

    float* out_s = reinterpret_cast<float*>(sm_u);
    #pragma unroll
    for (int p = 0; p < 2; ++p) {
        __syncthreads();
        #pragma unroll
        for (int im = 0; im < 2; ++im) {
            int m = (wm * 2 + im) * 16 + g;
            #pragma unroll
            for (int in = 0; in < 4; ++in) {
                int ni = wn * 4 + in;
                if ((ni >> 3) == p) {
                    int n = (ni & 7) * 8 + 2 * tt;
                    out_s[ n      * 132 + m    ] = acc[im][in][0];
                    out_s[(n + 1) * 132 + m    ] = acc[im][in][1];
                    out_s[ n      * 132 + m + 8] = acc[im][in][2];
                    out_s[(n + 1) * 132 + m + 8] = acc[im][in][3];
                }
            }
        }
        __syncthreads();
        #pragma unroll
        for (int j = 0; j < 16; ++j) {
            int idx = j * 512 + tid;
            int n = idx >> 7, m = idx & 127;
            g_conv[(b * 256 + (2 * gp + p) * 64 + n) * 1024 + mt * 128 + m]
                = out_s[n * 132 + m];
        }
    }
}

// ---------------- fused gate + qkv (R13 winner, unchanged) -----------------
__global__ void __launch_bounds__(512) k_gqkv(
    const float* __restrict__ bc,
    const float* __restrict__ Wci, const float* __restrict__ Wcf,
    const float* __restrict__ Wco,
    const float* __restrict__ qw,  const float* __restrict__ qb,
    const float* __restrict__ kw,  const float* __restrict__ kb,
    const float* __restrict__ vw,  const float* __restrict__ vb)
{
    __shared__ float h_s[32 * 128];
    __shared__ float w_s[96 * 33];

    const int pt   = blockIdx.x;
    const int b    = blockIdx.y;
    const int tid  = threadIdx.x;
    const int pos  = tid >> 2;
    const int och  = tid & 3;
    const int posg = pt * 128 + pos;

    float acc[24];
    #pragma unroll
    for (int j = 0; j < 24; ++j) {
        int oc = och * 24 + j;
        acc[j] = (oc < 16) ? qb[oc] : (oc < 32) ? kb[oc - 16] : vb[oc - 32];
    }

    for (int ch = 0; ch < 2; ++ch) {
        for (int i = tid; i < 3072; i += 512) {
            int oc = i >> 5, c = i & 31;
            int cg = ch * 32 + c;
            float wv = (oc < 16) ? qw[oc * 64 + cg]
                     : (oc < 32) ? kw[(oc - 16) * 64 + cg]
                                 : vw[(oc - 32) * 64 + cg];
            w_s[oc * 33 + c] = wv;
        }
        #pragma unroll
        for (int r = 0; r < 8; ++r) {
            int i = tid + r * 512;
            int c = i >> 7, p = i & 127;
            int cg = ch * 32 + c;
            int pg = pt * 128 + p;
            int idx = (b * 64 + cg) * 1024 + pg;
            int cb  = (b * 256 + cg) * 1024 + pg;
            float ic = g_conv[cb]              + bc[cg];
            float fc = g_conv[cb + 64 * 1024]  + bc[64 + cg];
            float gc = g_conv[cb + 128 * 1024] + bc[128 + cg];
            float oc = g_conv[cb + 192 * 1024] + bc[192 + cg];
            float cp = g_c[idx];
            int   wp = cg * 1024 + pg;
            float ii = sigf(ic + Wci[wp] * cp);
            float ff = sigf(fc + Wcf[wp] * cp);
            float nc = ff * cp + ii * tanh_fast(gc);
            float oo = sigf(oc + Wco[wp] * nc);
            g_c[idx] = nc;
            h_s[c * 128 + p] = oo * tanh_fast(nc);
        }
        __syncthreads();
        #pragma unroll 8
        for (int c = 0; c < 32; ++c) {
            float hv = h_s[c * 128 + pos];
            #pragma unroll
            for (int j = 0; j < 24; ++j)
                acc[j] += w_s[(och * 24 + j) * 33 + c] * hv;
        }
        __syncthreads();
    }

    if (och == 0) {
        #pragma unroll
        for (int j = 0; j < 16; ++j)
            g_q[(b * 16 + j) * 1024 + posg] = acc[j];
    }
    #pragma unroll
    for (int j = 0; j < 24; j += 2) {
        int oc = och * 24 + j;
        if (oc >= 16 && oc < 32) {
            int c2 = (oc - 16) >> 1;
            int o  = (b * 1024 + posg) * 8 + c2;
            g_k2h[o] = pack_bf16(acc[j], acc[j + 1]);
            g_k2l[o] = pack_bf16(bf16_lo(acc[j]), bf16_lo(acc[j + 1]));
        }
    }
    #pragma unroll
    for (int j = 0; j < 24; ++j) {
        int oc = och * 24 + j;
        float other = __shfl_xor_sync(0xffffffffu, acc[j], 4);
        if (oc >= 32 && ((pos & 1) == 0)) {
            int vc = oc - 32;
            int o  = (b * 64 + vc) * 512 + (posg >> 1);
            g_v2h[o] = pack_bf16(acc[j], other);
            g_v2l[o] = pack_bf16(bf16_lo(acc[j]), bf16_lo(other));
        }
    }
}

// ---------------- flash attention: no-max softmax + cp.async staging -------
// grid (8 n-tiles of 128 rows, 16 batch), 256 threads = 8 warps.
// Scores are bounded (|s| << 80) so exp(s) cannot overflow: the running max
// and z-rescale are dropped entirely; l accumulated as per-lane partials.
__global__ void __launch_bounds__(256) k_flash(
    const float* __restrict__ zw, const float* __restrict__ zb,
    float* __restrict__ out, int t)
{
    __shared__ uint32_t pool[12288];               // 48 KB: 2 x 6144 buffers

    const int b    = blockIdx.y;
    const int n0   = blockIdx.x * 128;
    const int tid  = threadIdx.x;
    const int w    = tid >> 5;
    const int lane = tid & 31;
    const int g    = lane >> 2, tt = lane & 3;
    const int rA   = w * 16 + g;
    const uint32_t sbase = smem_u32(pool);

    auto stage_cp = [&](int bufsel, int mc) {
        uint32_t base = sbase + bufsel * 24576;
        const uint32_t* khp = g_k2h + (b * 1024 + mc * 64) * 8;
        const uint32_t* klp = g_k2l + (b * 1024 + mc * 64) * 8;
        #pragma unroll
        for (int r = 0; r < 2; ++r) {
            int i = tid + r * 256;
            int m = i >> 3, c2 = i & 7;
            cpa4(base + (m * 12 + c2) * 4,         khp + i, 4u);
            cpa4(base + (768 + m * 12 + c2) * 4,   klp + i, 4u);
        }
        const uint32_t* vhp = g_v2h + b * 64 * 512 + mc * 32;
        const uint32_t* vlp = g_v2l + b * 64 * 512 + mc * 32;
        #pragma unroll
        for (int r = 0; r < 8; ++r) {
            int i = tid + r * 256;
            int c = i >> 5, mp = i & 31;
            cpa4(base + (1536 + c * 36 + mp) * 4, vhp + c * 512 + mp, 4u);
            cpa4(base + (3840 + c * 36 + mp) * 4, vlp + c * 512 + mp, 4u);
        }
    };

    // ---- stage q into buf1 region; stage chunk 0 via cp.async into buf0 ----
    float* q_s = reinterpret_cast<float*>(pool + 6144);   // [128][17]
    for (int i = tid; i < 2048; i += 256) {
        int c = i >> 7, r = i & 127;
        q_s[r * 17 + c] = g_q[(b * 16 + c) * 1024 + n0 + r];
    }
    stage_cp(0, 0);
    cpa_commit();
    __syncthreads();

    uint4 qh, ql;
    {
        float x0 = q_s[rA * 17 + 2 * tt],           x1 = q_s[rA * 17 + 2 * tt + 1];
        float x2 = q_s[(rA + 8) * 17 + 2 * tt],     x3 = q_s[(rA + 8) * 17 + 2 * tt + 1];
        float x4 = q_s[rA * 17 + 8 + 2 * tt],       x5 = q_s[rA * 17 + 9 + 2 * tt];
        float x6 = q_s[(rA + 8) * 17 + 8 + 2 * tt], x7 = q_s[(rA + 8) * 17 + 9 + 2 * tt];
        qh = make_uint4(pack_bf16(x0, x1), pack_bf16(x2, x3),
                        pack_bf16(x4, x5), pack_bf16(x6, x7));
        ql = make_uint4(pack_bf16(bf16_lo(x0), bf16_lo(x1)),
                        pack_bf16(bf16_lo(x2), bf16_lo(x3)),
                        pack_bf16(bf16_lo(x4), bf16_lo(x5)),
                        pack_bf16(bf16_lo(x6), bf16_lo(x7)));
    }
    cpa_wait0();
    __syncthreads();      // q reads done -> buf1 free for chunk 1 staging

    float z[8][4];
    #pragma unroll
    for (int cj = 0; cj < 8; ++cj)
        #pragma unroll
        for (int q = 0; q < 4; ++q) z[cj][q] = 0.f;
    float la = 0.f, lb = 0.f;        // per-lane partial row sums

    for (int mch = 0; mch < 16; ++mch) {
        uint32_t* cur = pool + (mch & 1) * 6144;
        if (mch < 15) { stage_cp((mch + 1) & 1, mch + 1); cpa_commit(); }

        // ---- S = q . k^T (128 x 64), 3-pass hi/lo ----
        float S[8][4];
        #pragma unroll
        for (int j = 0; j < 8; ++j)
            #pragma unroll
            for (int q = 0; q < 4; ++q) S[j][q] = 0.f;
        #pragma unroll
        for (int j = 0; j < 8; ++j) {
            int m = j * 8 + g;
            uint2 bh = make_uint2(cur[m * 12 + tt],       cur[m * 12 + tt + 4]);
            uint2 bl = make_uint2(cur[768 + m * 12 + tt], cur[768 + m * 12 + tt + 4]);
            mma_bf16(S[j], qh, bh);
            mma_bf16(S[j], qh, bl);
            mma_bf16(S[j], ql, bh);
        }

        // ---- exp (no max shift; scores bounded), accumulate lane partials --
        #pragma unroll
        for (int j = 0; j < 8; ++j) {
            S[j][0] = __expf(S[j][0]); la += S[j][0];
            S[j][1] = __expf(S[j][1]); la += S[j][1];
            S[j][2] = __expf(S[j][2]); lb += S[j][2];
            S[j][3] = __expf(S[j][3]); lb += S[j][3];
        }

        // ---- z += P @ v^T, 3-pass hi/lo; P frags direct from S regs ----
        #pragma unroll
        for (int ks = 0; ks < 4; ++ks) {
            uint4 ah = make_uint4(
                pack_bf16(S[2 * ks][0], S[2 * ks][1]),
                pack_bf16(S[2 * ks][2], S[2 * ks][3]),
                pack_bf16(S[2 * ks + 1][0], S[2 * ks + 1][1]),
                pack_bf16(S[2 * ks + 1][2], S[2 * ks + 1][3]));
            uint4 al = make_uint4(
                pack_bf16(bf16_lo(S[2 * ks][0]), bf16_lo(S[2 * ks][1])),
                pack_bf16(bf16_lo(S[2 * ks][2]), bf16_lo(S[2 * ks][3])),
                pack_bf16(bf16_lo(S[2 * ks + 1][0]), bf16_lo(S[2 * ks + 1][1])),
                pack_bf16(bf16_lo(S[2 * ks + 1][2]), bf16_lo(S[2 * ks + 1][3])));
            #pragma unroll
            for (int cj = 0; cj < 8; ++cj) {
                int c = cj * 8 + g;
                uint2 bh = make_uint2(cur[1536 + c * 36 + ks * 8 + tt],
                                      cur[1536 + c * 36 + ks * 8 + tt + 4]);
                uint2 bl = make_uint2(cur[3840 + c * 36 + ks * 8 + tt],
                                      cur[3840 + c * 36 + ks * 8 + tt + 4]);
                mma_bf16(z[cj], ah, bh);
                mma_bf16(z[cj], ah, bl);
                mma_bf16(z[cj], al, bh);
            }
        }

        cpa_wait0();
        __syncthreads();
    }

    // ---- final l reduction (over tt lanes) + normalize ----
    la += __shfl_xor_sync(0xffffffffu, la, 1);
    la += __shfl_xor_sync(0xffffffffu, la, 2);
    lb += __shfl_xor_sync(0xffffffffu, lb, 1);
    lb += __shfl_xor_sync(0xffffffffu, lb, 2);
    float lia = 1.f / la, lib = 1.f / lb;

    float* z_s  = reinterpret_cast<float*>(pool);          // [64][128]
    float* zw_s = reinterpret_cast<float*>(pool + 8192);   // 4096
    #pragma unroll
    for (int cj = 0; cj < 8; ++cj) {
        int c = cj * 8 + 2 * tt;
        z_s[ c      * 128 + w * 16 + g    ] = z[cj][0] * lia;
        z_s[(c + 1) * 128 + w * 16 + g    ] = z[cj][1] * lia;
        z_s[ c      * 128 + w * 16 + g + 8] = z[cj][2] * lib;
        z_s[(c + 1) * 128 + w * 16 + g + 8] = z[cj][3] * lib;
    }
    for (int i = tid; i < 4096; i += 256) zw_s[i] = zw[i];
    __syncthreads();

    const int l = lane;
    float acc2[8][4];
    #pragma unroll
    for (int ci = 0; ci < 8; ++ci) {
        float bv = zb[w * 8 + ci];
        #pragma unroll
        for (int i = 0; i < 4; ++i) acc2[ci][i] = bv;
    }
    #pragma unroll 8
    for (int c = 0; c < 64; ++c) {
        float pv[4];
        #pragma unroll
        for (int i = 0; i < 4; ++i) pv[i] = z_s[c * 128 + l + 32 * i];
        #pragma unroll
        for (int ci = 0; ci < 8; ++ci) {
            float wv = zw_s[(w * 8 + ci) * 64 + c];
            #pragma unroll
            for (int i = 0; i < 4; ++i) acc2[ci][i] += wv * pv[i];
        }
    }
    #pragma unroll
    for (int ci = 0; ci < 8; ++ci) {
        int oc = w * 8 + ci;
        #pragma unroll
        for (int i = 0; i < 4; ++i) {
            int n = n0 + l + 32 * i;
            out[((b * 64 + oc) * 16 + t) * 1024 + n] = acc2[ci][i];
        }
    }
    #pragma unroll
    for (int e = 0; e < 4; ++e) {
        #pragma unroll
        for (int i = 0; i < 4; ++i) {
            int n = n0 + l + 32 * i;
            int o = (b * 1024 + n) * 32 + w * 4 + e;
            g_Hph[o] = pack_bf16(acc2[2 * e][i], acc2[2 * e + 1][i]);
            g_Hpl[o] = pack_bf16(bf16_lo(acc2[2 * e][i]),
                                 bf16_lo(acc2[2 * e + 1][i]));
        }
    }
}

// ---------------- orchestration --------------------------------------------
extern "C" void kernel_launch(void* const* d_in, const int* in_sizes, int n_in,
                              void* d_out, int out_size)
{
    (void)in_sizes; (void)n_in; (void)out_size;
    const float* X   = (const float*)d_in[0];
    const float* Wc  = (const float*)d_in[1];
    const float* bcc = (const float*)d_in[2];
    const float* Wci = (const float*)d_in[3];
    const float* Wcf = (const float*)d_in[4];
    const float* Wco = (const float*)d_in[5];
    const float* qw  = (const float*)d_in[6];
    const float* qb  = (const float*)d_in[7];
    const float* kw  = (const float*)d_in[8];
    const float* kb  = (const float*)d_in[9];
    const float* vw  = (const float*)d_in[10];
    const float* vb  = (const float*)d_in[11];
    const float* zw  = (const float*)d_in[12];
    const float* zb  = (const float*)d_in[13];
    float* out = (float*)d_out;

    cudaFuncSetAttribute(k_conv_mma,
                         cudaFuncAttributeMaxDynamicSharedMemorySize, 131072);

    k_init <<<4096, 256>>>();
    k_prepx<<<1024, 256>>>(X);
    k_prepw<<<1152, 256>>>(Wc);
    for (int t = 0; t < NT; ++t) {
        k_conv_mma<<<dim3(8, 16, 2), 512, 131072>>>(t);
        k_gqkv    <<<dim3(8, 16),    512>>>(bcc, Wci, Wcf, Wco,
                                            qw, qb, kw, kb, vw, vb);
        k_flash   <<<dim3(8, 16),    256>>>(zw, zb, out, t);
    }
}